// round 5
// baseline (speedup 1.0000x reference)
#include <cuda_runtime.h>
#include <cuda_bf16.h>
#include <math.h>
#include <stdint.h>

#define NN   40000
#define EE   640000
#define GG   64
#define HH   4
#define CC   64
#define HC   256
#define NHID 1024
#define NOUT 768
#define NEG_SLOPE 0.2f

// ---------------- static device scratch ----------------
__device__ float g_bufA[(size_t)NN * HC];
__device__ float g_bufB[(size_t)NN * HC];
__device__ float g_as[NN * 4];
__device__ float g_ad[NN * 4];
__device__ int   g_cnt[NN];
__device__ int   g_cur[NN];
__device__ int   g_off[NN + 1];
__device__ int   g_csr[EE];                 // src node, sorted by dst
__device__ int   g_goff[GG + 1];
__device__ float g_pooled[GG * HC];
__device__ float g_hid[GG * NHID];
__device__ int   g_is64_e, g_is64_b;
__device__ int   g_bsum[160];
__device__ int   g_boff[160];
// pre-split weights: bf162 packed along K pairs: [kp=128][n=256], u32 = {bf16(B[2kp][n]), bf16(B[2kp+1][n])}
__device__ unsigned g_w1h[128 * 256], g_w1l[128 * 256];
__device__ unsigned g_w2h[128 * 256], g_w2l[128 * 256];
__device__ unsigned g_w3h[128 * 256], g_w3l[128 * 256];

__device__ __forceinline__ float lrelu(float v) {
    return v > 0.f ? v : NEG_SLOPE * v;
}

__device__ __forceinline__ int idx_at(const void* p, long long i, int is64) {
    if (is64) return (int)((const long long*)p)[i];
    return ((const int*)p)[i];
}

// ---------------- dtype detection ----------------
__global__ void k_detect(const void* ei, const void* batch) {
    if (threadIdx.x != 0 || blockIdx.x != 0) return;
    const int* e32 = (const int*)ei;
    int all0 = 1;
    for (int j = 1; j < 128; j += 2) if (e32[j] != 0) { all0 = 0; break; }
    g_is64_e = all0;
    const int* b32 = (const int*)batch;
    all0 = 1;
    for (int j = NN - 1; j > NN - 65; j -= 2) if (b32[j] != 0) { all0 = 0; break; }
    g_is64_b = all0;
}

// ---------------- prep: zero counters + split/pack weight matrices ----------------
__device__ __forceinline__ void pack_pair(float a, float b, unsigned& hi, unsigned& lo) {
    __nv_bfloat16 ha = __float2bfloat16(a);
    __nv_bfloat16 hb = __float2bfloat16(b);
    float la = a - __bfloat162float(ha);
    float lb = b - __bfloat162float(hb);
    __nv_bfloat162 hp = __halves2bfloat162(ha, hb);
    __nv_bfloat162 lp = __halves2bfloat162(__float2bfloat16(la), __float2bfloat16(lb));
    hi = *(unsigned*)&hp;
    lo = *(unsigned*)&lp;
}

__global__ void k_prep(const float* __restrict__ W1, const float* __restrict__ W2,
                       const float* __restrict__ W3) {
    int i = blockIdx.x * blockDim.x + threadIdx.x;
    if (i < NN) { g_cnt[i] = 0; g_cur[i] = 0; }
    if (i < 128 * 256) {
        int kp = i >> 8, n = i & 255;
        size_t i0 = (size_t)(2 * kp) * 256 + n;
        size_t i1 = i0 + 256;
        unsigned h, l;
        pack_pair(W1[i0], W1[i1], h, l); g_w1h[i] = h; g_w1l[i] = l;
        pack_pair(W2[i0], W2[i1], h, l); g_w2h[i] = h; g_w2l[i] = l;
        pack_pair(W3[i0], W3[i1], h, l); g_w3h[i] = h; g_w3l[i] = l;
    }
}

// ---------------- CSR ----------------
__global__ void k_count(const void* __restrict__ ei) {
    int e = blockIdx.x * blockDim.x + threadIdx.x;
    if (e < EE) atomicAdd(&g_cnt[idx_at(ei, (long long)EE + e, g_is64_e)], 1);
}

__global__ void k_gbounds(const void* __restrict__ batch) {
    int g = threadIdx.x;
    if (g > GG) return;
    int is64 = g_is64_b;
    int lo = 0, hi = NN;
    while (lo < hi) {
        int mid = (lo + hi) >> 1;
        if (idx_at(batch, mid, is64) < g) lo = mid + 1; else hi = mid;
    }
    g_goff[g] = lo;
}

__global__ void k_scan1() {
    __shared__ int sd[256];
    int b = blockIdx.x, t = threadIdx.x;
    int i = b * 256 + t;
    int v = (i < NN) ? g_cnt[i] : 0;
    sd[t] = v;
    __syncthreads();
#pragma unroll
    for (int o = 1; o < 256; o <<= 1) {
        int y = (t >= o) ? sd[t - o] : 0;
        __syncthreads();
        sd[t] += y;
        __syncthreads();
    }
    if (i < NN) g_off[i] = sd[t] - v;
    if (t == 255) g_bsum[b] = sd[255];
}

__global__ void k_scan2(int nb) {
    __shared__ int sd[256];
    int t = threadIdx.x;
    int v = (t < nb) ? g_bsum[t] : 0;
    sd[t] = v;
    __syncthreads();
#pragma unroll
    for (int o = 1; o < 256; o <<= 1) {
        int y = (t >= o) ? sd[t - o] : 0;
        __syncthreads();
        sd[t] += y;
        __syncthreads();
    }
    if (t < nb) g_boff[t] = sd[t] - v;
    if (t == 0) g_off[NN] = EE;
}

__global__ void k_scan3() {
    int i = blockIdx.x * blockDim.x + threadIdx.x;
    if (i < NN) g_off[i] += g_boff[blockIdx.x];
}

__global__ void k_fill(const void* __restrict__ ei) {
    int e = blockIdx.x * blockDim.x + threadIdx.x;
    if (e >= EE) return;
    int is64 = g_is64_e;
    int s = idx_at(ei, e, is64);
    int d = idx_at(ei, (long long)EE + e, is64);
    int pos = atomicAdd(&g_cur[d], 1);
    g_csr[g_off[d] + pos] = s;
}

// ---------------- bf16 3-term split tensor-core GEMM ----------------
// C[M,256] = A[M,256] @ B[256,256] with acc = Ah*Bh + Ah*Bl + Al*Bh (fp32 accum).
// Block 64x64 tile, 128 threads (4 warps, 2x2 of 32x32 warp tiles), K staged 64 at a time.
// Smem holds fragments pre-permuted into exact mma.m16n8k16 register layout:
//   sAh/sAl[(wr*2+mt)*4+kc][lane][reg j]   (u32 = bf162, j = b + 2d)
//   sB    [(wc*4+nt)*4+kc][lane][j]        (j0,j1 = Bh regs; j2,j3 = Bl regs)

__device__ __forceinline__ void mma_bf16(float* d, const uint4& a, unsigned b0, unsigned b1) {
    asm volatile(
        "mma.sync.aligned.m16n8k16.row.col.f32.bf16.bf16.f32 "
        "{%0,%1,%2,%3}, {%4,%5,%6,%7}, {%8,%9}, {%0,%1,%2,%3};\n"
        : "+f"(d[0]), "+f"(d[1]), "+f"(d[2]), "+f"(d[3])
        : "r"(a.x), "r"(a.y), "r"(a.z), "r"(a.w), "r"(b0), "r"(b1));
}

__global__ void __launch_bounds__(128) k_gemm_bf(const float* __restrict__ A,
                                                 const unsigned* __restrict__ Bh2,
                                                 const unsigned* __restrict__ Bl2,
                                                 float* __restrict__ C) {
    __shared__ unsigned sAh[2048], sAl[2048], sB[4096];

    int tid = threadIdx.x;
    int warp = tid >> 5, lane = tid & 31;
    int lm = lane >> 2;               // groupID 0..7
    int lk = lane & 3;                // thread in group
    int wr = warp & 1;                // warp row half (rows wr*32..)
    int wc = warp >> 1;               // warp col half
    int row0 = blockIdx.x * 64;
    int col0 = blockIdx.y * 64;

    float acc[2][4][4];
#pragma unroll
    for (int mt = 0; mt < 2; mt++)
#pragma unroll
        for (int nt = 0; nt < 4; nt++)
#pragma unroll
            for (int r = 0; r < 4; r++) acc[mt][nt][r] = 0.f;

    // A fill mapping: row = tid>>1, col segment = (tid&1)*32
    int ar = tid >> 1;
    int acseg = (tid & 1) * 32;
    int awr = ar >> 5, amt = (ar >> 4) & 1, ab = (ar >> 3) & 1, alm = ar & 7;
    // B fill mapping: local k-pair = tid>>2, n segment = (tid&3)*16
    int bkp = tid >> 2;
    int bnseg = (tid & 3) * 16;
    int bkc = bkp >> 3, bd = (bkp >> 2) & 1, blk = bkp & 3;

    for (int s = 0; s < 4; s++) {
        int k0 = s * 64;
        // ---- A fill: load fp32, split bf16 hi/lo, scatter to fragment layout ----
#pragma unroll
        for (int i = 0; i < 8; i++) {
            int c = acseg + i * 4;
            float4 v = *(const float4*)(A + (size_t)(row0 + ar) * 256 + k0 + c);
            int kc = c >> 4;
            int d = (c >> 3) & 1;
            int lk0 = (c >> 1) & 3;           // pair index within 8-k half: {0,2}
            int base = ((awr * 2 + amt) * 4 + kc) * 128 + ab + 2 * d;
            __nv_bfloat16 hx = __float2bfloat16(v.x), hy = __float2bfloat16(v.y);
            __nv_bfloat16 hz = __float2bfloat16(v.z), hw = __float2bfloat16(v.w);
            float lx = v.x - __bfloat162float(hx), ly = v.y - __bfloat162float(hy);
            float lz = v.z - __bfloat162float(hz), lw = v.w - __bfloat162float(hw);
            __nv_bfloat162 hp0 = __halves2bfloat162(hx, hy);
            __nv_bfloat162 hp1 = __halves2bfloat162(hz, hw);
            __nv_bfloat162 lp0 = __halves2bfloat162(__float2bfloat16(lx), __float2bfloat16(ly));
            __nv_bfloat162 lp1 = __halves2bfloat162(__float2bfloat16(lz), __float2bfloat16(lw));
            sAh[base + (alm * 4 + lk0) * 4]     = *(unsigned*)&hp0;
            sAh[base + (alm * 4 + lk0 + 1) * 4] = *(unsigned*)&hp1;
            sAl[base + (alm * 4 + lk0) * 4]     = *(unsigned*)&lp0;
            sAl[base + (alm * 4 + lk0 + 1) * 4] = *(unsigned*)&lp1;
        }
        // ---- B fill: pre-packed bf162 k-pairs, scatter to fragment layout ----
#pragma unroll
        for (int i = 0; i < 4; i++) {
            int n = bnseg + i * 4;
            size_t gi = (size_t)(k0 / 2 + bkp) * 256 + col0 + n;
            uint4 vh = *(const uint4*)(Bh2 + gi);
            uint4 vl = *(const uint4*)(Bl2 + gi);
            const unsigned* ph = (const unsigned*)&vh;
            const unsigned* pl = (const unsigned*)&vl;
#pragma unroll
            for (int m = 0; m < 4; m++) {
                int nn = n + m;
                int wcc = nn >> 5, nt = (nn >> 3) & 3, lmm = nn & 7;
                int base = ((wcc * 4 + nt) * 4 + bkc) * 128 + (lmm * 4 + blk) * 4;
                sB[base + bd]     = ph[m];
                sB[base + 2 + bd] = pl[m];
            }
        }
        __syncthreads();

        // ---- compute: 4 k16 chunks ----
#pragma unroll
        for (int kc = 0; kc < 4; kc++) {
            uint4 ah[2], al[2], bb[4];
#pragma unroll
            for (int mt = 0; mt < 2; mt++) {
                ah[mt] = *(const uint4*)&sAh[((wr * 2 + mt) * 4 + kc) * 128 + lane * 4];
                al[mt] = *(const uint4*)&sAl[((wr * 2 + mt) * 4 + kc) * 128 + lane * 4];
            }
#pragma unroll
            for (int nt = 0; nt < 4; nt++)
                bb[nt] = *(const uint4*)&sB[((wc * 4 + nt) * 4 + kc) * 128 + lane * 4];
#pragma unroll
            for (int mt = 0; mt < 2; mt++)
#pragma unroll
                for (int nt = 0; nt < 4; nt++) {
                    mma_bf16(acc[mt][nt], ah[mt], bb[nt].x, bb[nt].y);   // Ah*Bh
                    mma_bf16(acc[mt][nt], ah[mt], bb[nt].z, bb[nt].w);   // Ah*Bl
                    mma_bf16(acc[mt][nt], al[mt], bb[nt].x, bb[nt].y);   // Al*Bh
                }
        }
        __syncthreads();
    }

    // ---- store C ----
#pragma unroll
    for (int mt = 0; mt < 2; mt++) {
        int r = row0 + wr * 32 + mt * 16 + lm;
#pragma unroll
        for (int nt = 0; nt < 4; nt++) {
            int c = col0 + wc * 32 + nt * 8 + lk * 2;
            *(float2*)(C + (size_t)r * 256 + c)       = make_float2(acc[mt][nt][0], acc[mt][nt][1]);
            *(float2*)(C + (size_t)(r + 8) * 256 + c) = make_float2(acc[mt][nt][2], acc[mt][nt][3]);
        }
    }
}

// ---------------- per-node attention scalars ----------------
__global__ void k_alpha(const float* __restrict__ h, const float* __restrict__ a_s,
                        const float* __restrict__ a_d) {
    int gw = (blockIdx.x * blockDim.x + threadIdx.x) >> 5;
    int lane = threadIdx.x & 31;
    if (gw >= NN) return;
    const float* row = h + (size_t)gw * HC;
#pragma unroll
    for (int hh = 0; hh < HH; hh++) {
        float v1 = row[hh * 64 + lane];
        float v2 = row[hh * 64 + 32 + lane];
        float ps = v1 * __ldg(&a_s[hh * 64 + lane]) + v2 * __ldg(&a_s[hh * 64 + 32 + lane]);
        float pd = v1 * __ldg(&a_d[hh * 64 + lane]) + v2 * __ldg(&a_d[hh * 64 + 32 + lane]);
#pragma unroll
        for (int o = 16; o > 0; o >>= 1) {
            ps += __shfl_down_sync(0xffffffffu, ps, o);
            pd += __shfl_down_sync(0xffffffffu, pd, o);
        }
        if (lane == 0) {
            g_as[gw * 4 + hh] = ps;
            g_ad[gw * 4 + hh] = pd;
        }
    }
}

// ---------------- warp-per-node gather with inline softmax weights ----------------
template <bool RELU>
__global__ void k_gather(const float* __restrict__ h, const float* __restrict__ bias,
                         float* __restrict__ out) {
    int gw = (blockIdx.x * blockDim.x + threadIdx.x) >> 5;
    int lane = threadIdx.x & 31;
    if (gw >= NN) return;
    int s0 = g_off[gw], s1 = g_off[gw + 1];
    float4 dv = *(const float4*)(g_ad + gw * 4);
    float acc[8];
#pragma unroll
    for (int k = 0; k < 8; k++) acc[k] = 0.f;
    float den0 = 0.f, den1 = 0.f, den2 = 0.f, den3 = 0.f;

    for (int i = s0; i < s1; i++) {
        int s = __ldg(&g_csr[i]);
        float4 a = __ldg((const float4*)g_as + s);
        float w0 = __expf(lrelu(a.x + dv.x));
        float w1 = __expf(lrelu(a.y + dv.y));
        float w2 = __expf(lrelu(a.z + dv.z));
        float w3 = __expf(lrelu(a.w + dv.w));
        den0 += w0; den1 += w1; den2 += w2; den3 += w3;
        const float* hs = h + (size_t)s * HC;
        float wl[4] = {w0, w1, w2, w3};
#pragma unroll
        for (int k = 0; k < 8; k++) {
            acc[k] += wl[k >> 1] * __ldg(&hs[lane + 32 * k]);
        }
    }
    float4 av = *(const float4*)(g_as + gw * 4);
    float ws[4];
    ws[0] = __expf(lrelu(av.x + dv.x));
    ws[1] = __expf(lrelu(av.y + dv.y));
    ws[2] = __expf(lrelu(av.z + dv.z));
    ws[3] = __expf(lrelu(av.w + dv.w));
    float den[4] = {den0 + ws[0], den1 + ws[1], den2 + ws[2], den3 + ws[3]};
    const float* hn = h + (size_t)gw * HC;
    float* orow = out + (size_t)gw * HC;
#pragma unroll
    for (int k = 0; k < 8; k++) {
        int c = lane + 32 * k;
        int hh = k >> 1;
        float v = (acc[k] + ws[hh] * __ldg(&hn[c])) / den[hh] + __ldg(&bias[c]);
        if (RELU) v = fmaxf(v, 0.f);
        orow[c] = v;
    }
}

// ---------------- pooling + MLP head ----------------
__global__ void k_pool(const float* __restrict__ h3) {
    int g = blockIdx.x;
    int c = threadIdx.x;
    int s = g_goff[g], e = g_goff[g + 1];
    float sum = 0.f;
    for (int n = s; n < e; n++) sum += h3[(size_t)n * HC + c];
    float cntf = (float)(e - s);
    g_pooled[g * HC + c] = sum / fmaxf(cntf, 1.0f);
}

__global__ void k_mlp1(const float* __restrict__ Wm1, const float* __restrict__ bm1) {
    __shared__ float sp[HC];
    int g = blockIdx.x;
    int j = threadIdx.x;
    if (j < HC) sp[j] = g_pooled[g * HC + j];
    __syncthreads();
    float acc = __ldg(&bm1[j]);
    for (int k = 0; k < HC; k++) acc += sp[k] * __ldg(&Wm1[(size_t)k * NHID + j]);
    g_hid[g * NHID + j] = fmaxf(acc, 0.f);
}

__global__ void k_mlp2(const float* __restrict__ Wm2, const float* __restrict__ bm2,
                       float* __restrict__ out) {
    __shared__ float sp[NHID];
    int g = blockIdx.x;
    int j = threadIdx.x;
    for (int k = j; k < NHID; k += NOUT) sp[k] = g_hid[g * NHID + k];
    __syncthreads();
    float acc = __ldg(&bm2[j]);
    for (int k = 0; k < NHID; k++) acc += sp[k] * __ldg(&Wm2[(size_t)k * NOUT + j]);
    out[g * NOUT + j] = acc;
}

// ---------------- launch ----------------
extern "C" void kernel_launch(void* const* d_in, const int* in_sizes, int n_in,
                              void* d_out, int out_size) {
    const float* x     = (const float*)d_in[0];
    const void*  ei    = d_in[1];
    const void*  batch = d_in[2];
    const float* W1  = (const float*)d_in[3];
    const float* as1 = (const float*)d_in[4];
    const float* ad1 = (const float*)d_in[5];
    const float* b1  = (const float*)d_in[6];
    const float* W2  = (const float*)d_in[7];
    const float* as2 = (const float*)d_in[8];
    const float* ad2 = (const float*)d_in[9];
    const float* b2  = (const float*)d_in[10];
    const float* W3  = (const float*)d_in[11];
    const float* as3 = (const float*)d_in[12];
    const float* ad3 = (const float*)d_in[13];
    const float* b3  = (const float*)d_in[14];
    const float* Wm1 = (const float*)d_in[15];
    const float* bm1 = (const float*)d_in[16];
    const float* Wm2 = (const float*)d_in[17];
    const float* bm2 = (const float*)d_in[18];
    float* out = (float*)d_out;

    float *bufA, *bufB;
    unsigned *w1h, *w1l, *w2h, *w2l, *w3h, *w3l;
    cudaGetSymbolAddress((void**)&bufA, g_bufA);
    cudaGetSymbolAddress((void**)&bufB, g_bufB);
    cudaGetSymbolAddress((void**)&w1h, g_w1h);
    cudaGetSymbolAddress((void**)&w1l, g_w1l);
    cudaGetSymbolAddress((void**)&w2h, g_w2h);
    cudaGetSymbolAddress((void**)&w2l, g_w2l);
    cudaGetSymbolAddress((void**)&w3h, g_w3h);
    cudaGetSymbolAddress((void**)&w3l, g_w3l);

    const int TPB = 256;
    int nb_node = (NN + TPB - 1) / TPB;     // 157
    int nb_edge = (EE + TPB - 1) / TPB;
    int nb_warp = (NN * 32 + TPB - 1) / TPB;

    dim3 gemm_grid(NN / 64, HC / 64);

    // launch index 3 (0-based) is what ncu captures -> keep gemm there
    k_detect<<<1, 32>>>(ei, batch);                       // 0
    k_prep<<<nb_node, TPB>>>(W1, W2, W3);                 // 1
    k_count<<<nb_edge, TPB>>>(ei);                        // 2
    k_gemm_bf<<<gemm_grid, 128>>>(x, w1h, w1l, bufA);     // 3  <- profiled
    k_gbounds<<<1, 128>>>(batch);                         // 4
    k_scan1<<<nb_node, TPB>>>();                          // 5
    k_scan2<<<1, 256>>>(nb_node);                         // 6
    k_scan3<<<nb_node, TPB>>>();                          // 7
    k_fill<<<nb_edge, TPB>>>(ei);                         // 8

    // Layer 1 (gemm already done)
    k_alpha<<<nb_warp, TPB>>>(bufA, as1, ad1);
    k_gather<true><<<nb_warp, TPB>>>(bufA, b1, bufB);

    // Layer 2
    k_gemm_bf<<<gemm_grid, 128>>>(bufB, w2h, w2l, bufA);
    k_alpha<<<nb_warp, TPB>>>(bufA, as2, ad2);
    k_gather<true><<<nb_warp, TPB>>>(bufA, b2, bufB);

    // Layer 3 (no relu)
    k_gemm_bf<<<gemm_grid, 128>>>(bufB, w3h, w3l, bufA);
    k_alpha<<<nb_warp, TPB>>>(bufA, as3, ad3);
    k_gather<false><<<nb_warp, TPB>>>(bufA, b3, bufB);

    // Pool + MLP
    k_pool<<<GG, HC>>>(bufB);
    k_mlp1<<<GG, NHID>>>(Wm1, bm1);
    k_mlp2<<<GG, NOUT>>>(Wm2, bm2, out);
}

// round 6
// speedup vs baseline: 1.6357x; 1.6357x over previous
#include <cuda_runtime.h>
#include <cuda_bf16.h>
#include <math.h>
#include <stdint.h>

#define NN   40000
#define EE   640000
#define GG   64
#define HH   4
#define CC   64
#define HC   256
#define NHID 1024
#define NOUT 768
#define NEG_SLOPE 0.2f

// ---------------- static device scratch ----------------
__device__ float g_bufA[(size_t)NN * HC];        // gemm output h (fp32)
__device__ float g_bufB[(size_t)NN * HC];        // layer-3 gather output (fp32)
__device__ uint2 g_a2[(size_t)NN * 128];         // packed gemm input: (bf162 hi, bf162 lo) per k-pair
__device__ float g_as[NN * 4];
__device__ float g_ad[NN * 4];
__device__ int   g_cnt[NN];
__device__ int   g_cur[NN];
__device__ int   g_off[NN + 1];
__device__ int   g_csr[EE];
__device__ int   g_goff[GG + 1];
__device__ float g_pooled[GG * HC];
__device__ float g_hid[GG * NHID];
__device__ int   g_is64_e, g_is64_b;
__device__ int   g_bsum[160];
__device__ int   g_boff[160];
// B in mma-fragment order: idx = (ntg*16 + kc)*32 + lane, uint4 = {bh0, bh1, bl0, bl1}
__device__ uint4 g_bf1[16384], g_bf2[16384], g_bf3[16384];

__device__ __forceinline__ float lrelu(float v) {
    return v > 0.f ? v : NEG_SLOPE * v;
}

__device__ __forceinline__ int idx_at(const void* p, long long i, int is64) {
    if (is64) return (int)((const long long*)p)[i];
    return ((const int*)p)[i];
}

__device__ __forceinline__ void pack_pair(float a, float b, unsigned& hi, unsigned& lo) {
    __nv_bfloat16 ha = __float2bfloat16(a);
    __nv_bfloat16 hb = __float2bfloat16(b);
    float la = a - __bfloat162float(ha);
    float lb = b - __bfloat162float(hb);
    __nv_bfloat162 hp = __halves2bfloat162(ha, hb);
    __nv_bfloat162 lp = __halves2bfloat162(__float2bfloat16(la), __float2bfloat16(lb));
    hi = *(unsigned*)&hp;
    lo = *(unsigned*)&lp;
}

// ---------------- dtype detection ----------------
__global__ void k_detect(const void* ei, const void* batch) {
    if (threadIdx.x != 0 || blockIdx.x != 0) return;
    const int* e32 = (const int*)ei;
    int all0 = 1;
    for (int j = 1; j < 128; j += 2) if (e32[j] != 0) { all0 = 0; break; }
    g_is64_e = all0;
    const int* b32 = (const int*)batch;
    all0 = 1;
    for (int j = NN - 1; j > NN - 65; j -= 2) if (b32[j] != 0) { all0 = 0; break; }
    g_is64_b = all0;
}

// ---------------- prep: zero counters + build B fragment arrays ----------------
__global__ void k_prep(const float* __restrict__ W1, const float* __restrict__ W2,
                       const float* __restrict__ W3) {
    int i = blockIdx.x * blockDim.x + threadIdx.x;
    if (i < NN) { g_cnt[i] = 0; g_cur[i] = 0; }
    if (i < 16384) {
        int ntg = i >> 9;          // 0..31 (n8 tile)
        int kc  = (i >> 5) & 15;   // 0..15 (k16 chunk)
        int lane = i & 31;
        int lm = lane >> 2, lk = lane & 3;
        int n = ntg * 8 + lm;
        int k0 = kc * 16 + 2 * lk;     // b0 rows k0,k0+1 ; b1 rows k0+8,k0+9
        uint4 f;
        {
            pack_pair(W1[(size_t)k0 * 256 + n], W1[(size_t)(k0 + 1) * 256 + n], f.x, f.z);
            pack_pair(W1[(size_t)(k0 + 8) * 256 + n], W1[(size_t)(k0 + 9) * 256 + n], f.y, f.w);
            g_bf1[i] = f;
        }
        {
            pack_pair(W2[(size_t)k0 * 256 + n], W2[(size_t)(k0 + 1) * 256 + n], f.x, f.z);
            pack_pair(W2[(size_t)(k0 + 8) * 256 + n], W2[(size_t)(k0 + 9) * 256 + n], f.y, f.w);
            g_bf2[i] = f;
        }
        {
            pack_pair(W3[(size_t)k0 * 256 + n], W3[(size_t)(k0 + 1) * 256 + n], f.x, f.z);
            pack_pair(W3[(size_t)(k0 + 8) * 256 + n], W3[(size_t)(k0 + 9) * 256 + n], f.y, f.w);
            g_bf3[i] = f;
        }
    }
}

// ---------------- split x into packed A2 ----------------
__global__ void k_split(const float* __restrict__ x) {
    int i = blockIdx.x * blockDim.x + threadIdx.x;
    if (i >= NN * 128) return;
    float2 v = ((const float2*)x)[i];
    uint2 o;
    pack_pair(v.x, v.y, o.x, o.y);
    g_a2[i] = o;
}

// ---------------- CSR ----------------
__global__ void k_count(const void* __restrict__ ei) {
    int e = blockIdx.x * blockDim.x + threadIdx.x;
    if (e < EE) atomicAdd(&g_cnt[idx_at(ei, (long long)EE + e, g_is64_e)], 1);
}

__global__ void k_gbounds(const void* __restrict__ batch) {
    int g = threadIdx.x;
    if (g > GG) return;
    int is64 = g_is64_b;
    int lo = 0, hi = NN;
    while (lo < hi) {
        int mid = (lo + hi) >> 1;
        if (idx_at(batch, mid, is64) < g) lo = mid + 1; else hi = mid;
    }
    g_goff[g] = lo;
}

__global__ void k_scan1() {
    __shared__ int sd[256];
    int b = blockIdx.x, t = threadIdx.x;
    int i = b * 256 + t;
    int v = (i < NN) ? g_cnt[i] : 0;
    sd[t] = v;
    __syncthreads();
#pragma unroll
    for (int o = 1; o < 256; o <<= 1) {
        int y = (t >= o) ? sd[t - o] : 0;
        __syncthreads();
        sd[t] += y;
        __syncthreads();
    }
    if (i < NN) g_off[i] = sd[t] - v;
    if (t == 255) g_bsum[b] = sd[255];
}

__global__ void k_scan2(int nb) {
    __shared__ int sd[256];
    int t = threadIdx.x;
    int v = (t < nb) ? g_bsum[t] : 0;
    sd[t] = v;
    __syncthreads();
#pragma unroll
    for (int o = 1; o < 256; o <<= 1) {
        int y = (t >= o) ? sd[t - o] : 0;
        __syncthreads();
        sd[t] += y;
        __syncthreads();
    }
    if (t < nb) g_boff[t] = sd[t] - v;
    if (t == 0) g_off[NN] = EE;
}

__global__ void k_scan3() {
    int i = blockIdx.x * blockDim.x + threadIdx.x;
    if (i < NN) g_off[i] += g_boff[blockIdx.x];
}

__global__ void k_fill(const void* __restrict__ ei) {
    int e = blockIdx.x * blockDim.x + threadIdx.x;
    if (e >= EE) return;
    int is64 = g_is64_e;
    int s = idx_at(ei, e, is64);
    int d = idx_at(ei, (long long)EE + e, is64);
    int pos = atomicAdd(&g_cur[d], 1);
    g_csr[g_off[d] + pos] = s;
}

// ---------------- smem-free bf16 3-term tensor-core GEMM ----------------
// C[M,256] = A[M,256] @ B[256,256]; acc = Ah*Bh + Ah*Bl + Al*Bh (fp32 accum).
// Block: 64x128 tile, 128 threads (4 warps, 2m x 2n), warp tile 32x64.
// A from packed uint2 (hi,lo bf162 per k-pair); B from fragment-ordered uint4 (L1-resident).

__device__ __forceinline__ void mma_bf16(float* d, const uint4& a, unsigned b0, unsigned b1) {
    asm volatile(
        "mma.sync.aligned.m16n8k16.row.col.f32.bf16.bf16.f32 "
        "{%0,%1,%2,%3}, {%4,%5,%6,%7}, {%8,%9}, {%0,%1,%2,%3};\n"
        : "+f"(d[0]), "+f"(d[1]), "+f"(d[2]), "+f"(d[3])
        : "r"(a.x), "r"(a.y), "r"(a.z), "r"(a.w), "r"(b0), "r"(b1));
}

__global__ void __launch_bounds__(128, 3) k_gemm_bf(const uint2* __restrict__ A2,
                                                    const uint4* __restrict__ Bf,
                                                    float* __restrict__ C) {
    int tid = threadIdx.x;
    int warp = tid >> 5, lane = tid & 31;
    int lm = lane >> 2, lk = lane & 3;
    int wm = warp & 1, wc = warp >> 1;
    int row0 = blockIdx.x * 64 + wm * 32;     // warp's 32-row band
    int ntg0 = blockIdx.y * 16 + wc * 8;      // warp's first n8 tile

    float acc[2][8][4];
#pragma unroll
    for (int mt = 0; mt < 2; mt++)
#pragma unroll
        for (int nt = 0; nt < 8; nt++)
#pragma unroll
            for (int r = 0; r < 4; r++) acc[mt][nt][r] = 0.f;

    const uint2* a0 = A2 + (size_t)(row0 + lm) * 128 + lk;   // row lm
    const uint4* bp = Bf + ntg0 * 512 + lane;                 // (ntg0*16+0)*32 + lane

#pragma unroll
    for (int kc = 0; kc < 16; kc++) {
        int kpo = kc * 8;
        uint4 ah[2], al[2];
#pragma unroll
        for (int mt = 0; mt < 2; mt++) {
            const uint2* am = a0 + mt * (16 * 128);
            uint2 f0 = __ldg(am + kpo);                // (row lm,    kp)
            uint2 f1 = __ldg(am + 8 * 128 + kpo);      // (row lm+8,  kp)
            uint2 f2 = __ldg(am + kpo + 4);            // (row lm,    kp+4)
            uint2 f3 = __ldg(am + 8 * 128 + kpo + 4);  // (row lm+8,  kp+4)
            ah[mt] = make_uint4(f0.x, f1.x, f2.x, f3.x);
            al[mt] = make_uint4(f0.y, f1.y, f2.y, f3.y);
        }
        uint4 bb[8];
#pragma unroll
        for (int nt = 0; nt < 8; nt++)
            bb[nt] = __ldg(bp + nt * 512 + kc * 32);
#pragma unroll
        for (int mt = 0; mt < 2; mt++)
#pragma unroll
            for (int nt = 0; nt < 8; nt++) {
                mma_bf16(acc[mt][nt], ah[mt], bb[nt].x, bb[nt].y);   // Ah*Bh
                mma_bf16(acc[mt][nt], ah[mt], bb[nt].z, bb[nt].w);   // Ah*Bl
                mma_bf16(acc[mt][nt], al[mt], bb[nt].x, bb[nt].y);   // Al*Bh
            }
    }

#pragma unroll
    for (int mt = 0; mt < 2; mt++) {
        int r = row0 + mt * 16 + lm;
#pragma unroll
        for (int nt = 0; nt < 8; nt++) {
            int c = (ntg0 + nt) * 8 + lk * 2;
            *(float2*)(C + (size_t)r * 256 + c)       = make_float2(acc[mt][nt][0], acc[mt][nt][1]);
            *(float2*)(C + (size_t)(r + 8) * 256 + c) = make_float2(acc[mt][nt][2], acc[mt][nt][3]);
        }
    }
}

// ---------------- per-node attention scalars ----------------
__global__ void k_alpha(const float* __restrict__ h, const float* __restrict__ a_s,
                        const float* __restrict__ a_d) {
    int gw = (blockIdx.x * blockDim.x + threadIdx.x) >> 5;
    int lane = threadIdx.x & 31;
    if (gw >= NN) return;
    const float* row = h + (size_t)gw * HC;
#pragma unroll
    for (int hh = 0; hh < HH; hh++) {
        float v1 = row[hh * 64 + lane];
        float v2 = row[hh * 64 + 32 + lane];
        float ps = v1 * __ldg(&a_s[hh * 64 + lane]) + v2 * __ldg(&a_s[hh * 64 + 32 + lane]);
        float pd = v1 * __ldg(&a_d[hh * 64 + lane]) + v2 * __ldg(&a_d[hh * 64 + 32 + lane]);
#pragma unroll
        for (int o = 16; o > 0; o >>= 1) {
            ps += __shfl_down_sync(0xffffffffu, ps, o);
            pd += __shfl_down_sync(0xffffffffu, pd, o);
        }
        if (lane == 0) {
            g_as[gw * 4 + hh] = ps;
            g_ad[gw * 4 + hh] = pd;
        }
    }
}

// ---------------- warp-per-node gather; packs output for the next GEMM ----------------
// Thread owns float2 col-pairs at cols 2*lane + 64*j (j=0..3); head of pair j is j.
template <bool RELU, bool PACK>
__global__ void k_gather(const float* __restrict__ h, const float* __restrict__ bias,
                         float* __restrict__ out) {
    int gw = (blockIdx.x * blockDim.x + threadIdx.x) >> 5;
    int lane = threadIdx.x & 31;
    if (gw >= NN) return;
    int s0 = g_off[gw], s1 = g_off[gw + 1];
    float4 dv = *(const float4*)(g_ad + gw * 4);
    float2 acc[4];
#pragma unroll
    for (int j = 0; j < 4; j++) acc[j] = make_float2(0.f, 0.f);
    float den0 = 0.f, den1 = 0.f, den2 = 0.f, den3 = 0.f;

    for (int i = s0; i < s1; i++) {
        int s = __ldg(&g_csr[i]);
        float4 a = __ldg((const float4*)g_as + s);
        float w0 = __expf(lrelu(a.x + dv.x));
        float w1 = __expf(lrelu(a.y + dv.y));
        float w2 = __expf(lrelu(a.z + dv.z));
        float w3 = __expf(lrelu(a.w + dv.w));
        den0 += w0; den1 += w1; den2 += w2; den3 += w3;
        const float2* hs = (const float2*)(h + (size_t)s * HC);
        float wl[4] = {w0, w1, w2, w3};
#pragma unroll
        for (int j = 0; j < 4; j++) {
            float2 v = __ldg(&hs[lane + 32 * j]);
            acc[j].x += wl[j] * v.x;
            acc[j].y += wl[j] * v.y;
        }
    }
    float4 av = *(const float4*)(g_as + gw * 4);
    float ws[4];
    ws[0] = __expf(lrelu(av.x + dv.x));
    ws[1] = __expf(lrelu(av.y + dv.y));
    ws[2] = __expf(lrelu(av.z + dv.z));
    ws[3] = __expf(lrelu(av.w + dv.w));
    float den[4] = {den0 + ws[0], den1 + ws[1], den2 + ws[2], den3 + ws[3]};
    const float2* hn = (const float2*)(h + (size_t)gw * HC);
    const float2* bias2 = (const float2*)bias;
#pragma unroll
    for (int j = 0; j < 4; j++) {
        int kp = lane + 32 * j;
        float2 hv = __ldg(&hn[kp]);
        float2 bv = __ldg(&bias2[kp]);
        float inv = 1.f / den[j];
        float vx = (acc[j].x + ws[j] * hv.x) * inv + bv.x;
        float vy = (acc[j].y + ws[j] * hv.y) * inv + bv.y;
        if (RELU) { vx = fmaxf(vx, 0.f); vy = fmaxf(vy, 0.f); }
        if (PACK) {
            uint2 o;
            pack_pair(vx, vy, o.x, o.y);
            g_a2[(size_t)gw * 128 + kp] = o;
        } else {
            ((float2*)(out + (size_t)gw * HC))[kp] = make_float2(vx, vy);
        }
    }
}

// ---------------- pooling + MLP head ----------------
__global__ void k_pool(const float* __restrict__ h3) {
    int g = blockIdx.x;
    int c = threadIdx.x;
    int s = g_goff[g], e = g_goff[g + 1];
    float sum = 0.f;
    for (int n = s; n < e; n++) sum += h3[(size_t)n * HC + c];
    float cntf = (float)(e - s);
    g_pooled[g * HC + c] = sum / fmaxf(cntf, 1.0f);
}

__global__ void k_mlp1(const float* __restrict__ Wm1, const float* __restrict__ bm1) {
    __shared__ float sp[HC];
    int g = blockIdx.x;
    int j = threadIdx.x;
    if (j < HC) sp[j] = g_pooled[g * HC + j];
    __syncthreads();
    float acc = __ldg(&bm1[j]);
    for (int k = 0; k < HC; k++) acc += sp[k] * __ldg(&Wm1[(size_t)k * NHID + j]);
    g_hid[g * NHID + j] = fmaxf(acc, 0.f);
}

__global__ void k_mlp2(const float* __restrict__ Wm2, const float* __restrict__ bm2,
                       float* __restrict__ out) {
    __shared__ float sp[NHID];
    int g = blockIdx.x;
    int j = threadIdx.x;
    for (int k = j; k < NHID; k += NOUT) sp[k] = g_hid[g * NHID + k];
    __syncthreads();
    float acc = __ldg(&bm2[j]);
    for (int k = 0; k < NHID; k++) acc += sp[k] * __ldg(&Wm2[(size_t)k * NOUT + j]);
    out[g * NOUT + j] = acc;
}

// ---------------- launch ----------------
extern "C" void kernel_launch(void* const* d_in, const int* in_sizes, int n_in,
                              void* d_out, int out_size) {
    const float* x     = (const float*)d_in[0];
    const void*  ei    = d_in[1];
    const void*  batch = d_in[2];
    const float* W1  = (const float*)d_in[3];
    const float* as1 = (const float*)d_in[4];
    const float* ad1 = (const float*)d_in[5];
    const float* b1  = (const float*)d_in[6];
    const float* W2  = (const float*)d_in[7];
    const float* as2 = (const float*)d_in[8];
    const float* ad2 = (const float*)d_in[9];
    const float* b2  = (const float*)d_in[10];
    const float* W3  = (const float*)d_in[11];
    const float* as3 = (const float*)d_in[12];
    const float* ad3 = (const float*)d_in[13];
    const float* b3  = (const float*)d_in[14];
    const float* Wm1 = (const float*)d_in[15];
    const float* bm1 = (const float*)d_in[16];
    const float* Wm2 = (const float*)d_in[17];
    const float* bm2 = (const float*)d_in[18];
    float* out = (float*)d_out;

    float *bufA, *bufB;
    uint2* a2;
    uint4 *bf1, *bf2, *bf3;
    cudaGetSymbolAddress((void**)&bufA, g_bufA);
    cudaGetSymbolAddress((void**)&bufB, g_bufB);
    cudaGetSymbolAddress((void**)&a2, g_a2);
    cudaGetSymbolAddress((void**)&bf1, g_bf1);
    cudaGetSymbolAddress((void**)&bf2, g_bf2);
    cudaGetSymbolAddress((void**)&bf3, g_bf3);

    const int TPB = 256;
    int nb_node = (NN + TPB - 1) / TPB;     // 157
    int nb_edge = (EE + TPB - 1) / TPB;
    int nb_warp = (NN * 32 + TPB - 1) / TPB;
    int nb_split = (NN * 128 + TPB - 1) / TPB;

    dim3 gemm_grid(NN / 64, 2);

    // launch index 3 (0-based) is what ncu captures -> keep gemm there
    k_detect<<<1, 32>>>(ei, batch);                       // 0
    k_prep<<<nb_node, TPB>>>(W1, W2, W3);                 // 1
    k_split<<<nb_split, TPB>>>(x);                        // 2
    k_gemm_bf<<<gemm_grid, 128>>>(a2, bf1, bufA);         // 3  <- profiled
    k_count<<<nb_edge, TPB>>>(ei);                        // 4
    k_gbounds<<<1, 128>>>(batch);                         // 5
    k_scan1<<<nb_node, TPB>>>();                          // 6
    k_scan2<<<1, 256>>>(nb_node);                         // 7
    k_scan3<<<nb_node, TPB>>>();                          // 8
    k_fill<<<nb_edge, TPB>>>(ei);                         // 9

    // Layer 1 (gemm already done)
    k_alpha<<<nb_warp, TPB>>>(bufA, as1, ad1);
    k_gather<true, true><<<nb_warp, TPB>>>(bufA, b1, bufB);

    // Layer 2
    k_gemm_bf<<<gemm_grid, 128>>>(a2, bf2, bufA);
    k_alpha<<<nb_warp, TPB>>>(bufA, as2, ad2);
    k_gather<true, true><<<nb_warp, TPB>>>(bufA, b2, bufB);

    // Layer 3 (no relu, fp32 out for pooling)
    k_gemm_bf<<<gemm_grid, 128>>>(a2, bf3, bufA);
    k_alpha<<<nb_warp, TPB>>>(bufA, as3, ad3);
    k_gather<false, false><<<nb_warp, TPB>>>(bufA, b3, bufB);

    // Pool + MLP
    k_pool<<<GG, HC>>>(bufB);
    k_mlp1<<<GG, NHID>>>(Wm1, bm1);
    k_mlp2<<<GG, NOUT>>>(Wm2, bm2, out);
}

// round 7
// speedup vs baseline: 1.6630x; 1.0167x over previous
#include <cuda_runtime.h>
#include <cuda_bf16.h>
#include <cuda_fp16.h>
#include <math.h>
#include <stdint.h>

#define NN   40000
#define EE   640000
#define GG   64
#define HH   4
#define CC   64
#define HC   256
#define NHID 1024
#define NOUT 768
#define NEG_SLOPE 0.2f

// ---------------- static device scratch ----------------
__device__ __half2 g_h16[(size_t)NN * 128];      // gemm output h (fp16 pairs) for gather
__device__ float g_bufB[(size_t)NN * HC];        // layer-3 gather output (fp32)
__device__ uint2 g_a2[(size_t)NN * 128];         // packed gemm input: (bf162 hi, bf162 lo) per k-pair
__device__ float g_as[NN * 4];
__device__ float g_ad[NN * 4];
__device__ int   g_cnt[NN];
__device__ int   g_cur[NN];
__device__ int   g_off[NN + 1];
__device__ int   g_csr[EE];
__device__ int   g_goff[GG + 1];
__device__ float g_pooled[GG * HC];
__device__ float g_hid[GG * NHID];
__device__ int   g_is64_e, g_is64_b;
__device__ int   g_bsum[160];
__device__ int   g_boff[160];
// B in mma-fragment order: idx = (ntg*16 + kc)*32 + lane, uint4 = {bh0, bh1, bl0, bl1}
__device__ uint4 g_bf1[16384], g_bf2[16384], g_bf3[16384];

__device__ __forceinline__ float lrelu(float v) {
    return v > 0.f ? v : NEG_SLOPE * v;
}

__device__ __forceinline__ int idx_at(const void* p, long long i, int is64) {
    if (is64) return (int)((const long long*)p)[i];
    return ((const int*)p)[i];
}

__device__ __forceinline__ void pack_pair(float a, float b, unsigned& hi, unsigned& lo) {
    __nv_bfloat16 ha = __float2bfloat16(a);
    __nv_bfloat16 hb = __float2bfloat16(b);
    float la = a - __bfloat162float(ha);
    float lb = b - __bfloat162float(hb);
    __nv_bfloat162 hp = __halves2bfloat162(ha, hb);
    __nv_bfloat162 lp = __halves2bfloat162(__float2bfloat16(la), __float2bfloat16(lb));
    hi = *(unsigned*)&hp;
    lo = *(unsigned*)&lp;
}

// ---------------- dtype detection ----------------
__global__ void k_detect(const void* ei, const void* batch) {
    if (threadIdx.x != 0 || blockIdx.x != 0) return;
    const int* e32 = (const int*)ei;
    int all0 = 1;
    for (int j = 1; j < 128; j += 2) if (e32[j] != 0) { all0 = 0; break; }
    g_is64_e = all0;
    const int* b32 = (const int*)batch;
    all0 = 1;
    for (int j = NN - 1; j > NN - 65; j -= 2) if (b32[j] != 0) { all0 = 0; break; }
    g_is64_b = all0;
}

// ---------------- prep: zero counters + build B fragment arrays ----------------
__global__ void k_prep(const float* __restrict__ W1, const float* __restrict__ W2,
                       const float* __restrict__ W3) {
    int i = blockIdx.x * blockDim.x + threadIdx.x;
    if (i < NN) { g_cnt[i] = 0; g_cur[i] = 0; }
    if (i < 16384) {
        int ntg = i >> 9;
        int kc  = (i >> 5) & 15;
        int lane = i & 31;
        int lm = lane >> 2, lk = lane & 3;
        int n = ntg * 8 + lm;
        int k0 = kc * 16 + 2 * lk;
        uint4 f;
        {
            pack_pair(W1[(size_t)k0 * 256 + n], W1[(size_t)(k0 + 1) * 256 + n], f.x, f.z);
            pack_pair(W1[(size_t)(k0 + 8) * 256 + n], W1[(size_t)(k0 + 9) * 256 + n], f.y, f.w);
            g_bf1[i] = f;
        }
        {
            pack_pair(W2[(size_t)k0 * 256 + n], W2[(size_t)(k0 + 1) * 256 + n], f.x, f.z);
            pack_pair(W2[(size_t)(k0 + 8) * 256 + n], W2[(size_t)(k0 + 9) * 256 + n], f.y, f.w);
            g_bf2[i] = f;
        }
        {
            pack_pair(W3[(size_t)k0 * 256 + n], W3[(size_t)(k0 + 1) * 256 + n], f.x, f.z);
            pack_pair(W3[(size_t)(k0 + 8) * 256 + n], W3[(size_t)(k0 + 9) * 256 + n], f.y, f.w);
            g_bf3[i] = f;
        }
    }
}

// ---------------- split x into packed A2 ----------------
__global__ void k_split(const float* __restrict__ x) {
    int i = blockIdx.x * blockDim.x + threadIdx.x;
    if (i >= NN * 128) return;
    float2 v = ((const float2*)x)[i];
    uint2 o;
    pack_pair(v.x, v.y, o.x, o.y);
    g_a2[i] = o;
}

// ---------------- CSR ----------------
__global__ void k_count(const void* __restrict__ ei) {
    int e = blockIdx.x * blockDim.x + threadIdx.x;
    if (e < EE) atomicAdd(&g_cnt[idx_at(ei, (long long)EE + e, g_is64_e)], 1);
}

__global__ void k_gbounds(const void* __restrict__ batch) {
    int g = threadIdx.x;
    if (g > GG) return;
    int is64 = g_is64_b;
    int lo = 0, hi = NN;
    while (lo < hi) {
        int mid = (lo + hi) >> 1;
        if (idx_at(batch, mid, is64) < g) lo = mid + 1; else hi = mid;
    }
    g_goff[g] = lo;
}

__global__ void k_scan1() {
    __shared__ int sd[256];
    int b = blockIdx.x, t = threadIdx.x;
    int i = b * 256 + t;
    int v = (i < NN) ? g_cnt[i] : 0;
    sd[t] = v;
    __syncthreads();
#pragma unroll
    for (int o = 1; o < 256; o <<= 1) {
        int y = (t >= o) ? sd[t - o] : 0;
        __syncthreads();
        sd[t] += y;
        __syncthreads();
    }
    if (i < NN) g_off[i] = sd[t] - v;
    if (t == 255) g_bsum[b] = sd[255];
}

__global__ void k_scan2(int nb) {
    __shared__ int sd[256];
    int t = threadIdx.x;
    int v = (t < nb) ? g_bsum[t] : 0;
    sd[t] = v;
    __syncthreads();
#pragma unroll
    for (int o = 1; o < 256; o <<= 1) {
        int y = (t >= o) ? sd[t - o] : 0;
        __syncthreads();
        sd[t] += y;
        __syncthreads();
    }
    if (t < nb) g_boff[t] = sd[t] - v;
    if (t == 0) g_off[NN] = EE;
}

__global__ void k_scan3() {
    int i = blockIdx.x * blockDim.x + threadIdx.x;
    if (i < NN) g_off[i] += g_boff[blockIdx.x];
}

__global__ void k_fill(const void* __restrict__ ei) {
    int e = blockIdx.x * blockDim.x + threadIdx.x;
    if (e >= EE) return;
    int is64 = g_is64_e;
    int s = idx_at(ei, e, is64);
    int d = idx_at(ei, (long long)EE + e, is64);
    int pos = atomicAdd(&g_cur[d], 1);
    g_csr[g_off[d] + pos] = s;
}

// ---------------- smem-free bf16 3-term tensor-core GEMM + fused alpha + fp16 h out ----------------
// h[M,256] = A[M,256] @ B[256,256]; acc = Ah*Bh + Ah*Bl + Al*Bh (fp32 accum).
// Block: 64x128 tile, 128 threads (4 warps, 2m x 2n), warp tile 32x64 = one full head.
// Epilogue: writes h as half2 AND computes alpha_src/dst = h . a_s/a_d per (row, head) exactly.

__device__ __forceinline__ void mma_bf16(float* d, const uint4& a, unsigned b0, unsigned b1) {
    asm volatile(
        "mma.sync.aligned.m16n8k16.row.col.f32.bf16.bf16.f32 "
        "{%0,%1,%2,%3}, {%4,%5,%6,%7}, {%8,%9}, {%0,%1,%2,%3};\n"
        : "+f"(d[0]), "+f"(d[1]), "+f"(d[2]), "+f"(d[3])
        : "r"(a.x), "r"(a.y), "r"(a.z), "r"(a.w), "r"(b0), "r"(b1));
}

__global__ void __launch_bounds__(128, 3) k_gemm_bf(const uint2* __restrict__ A2,
                                                    const uint4* __restrict__ Bf,
                                                    const float* __restrict__ a_s,
                                                    const float* __restrict__ a_d,
                                                    __half2* __restrict__ Hout) {
    int tid = threadIdx.x;
    int warp = tid >> 5, lane = tid & 31;
    int lm = lane >> 2, lk = lane & 3;
    int wm = warp & 1, wc = warp >> 1;
    int row0 = blockIdx.x * 64 + wm * 32;
    int ntg0 = blockIdx.y * 16 + wc * 8;

    float acc[2][8][4];
#pragma unroll
    for (int mt = 0; mt < 2; mt++)
#pragma unroll
        for (int nt = 0; nt < 8; nt++)
#pragma unroll
            for (int r = 0; r < 4; r++) acc[mt][nt][r] = 0.f;

    const uint2* a0 = A2 + (size_t)(row0 + lm) * 128 + lk;
    const uint4* bp = Bf + ntg0 * 512 + lane;

#pragma unroll
    for (int kc = 0; kc < 16; kc++) {
        int kpo = kc * 8;
        uint4 ah[2], al[2];
#pragma unroll
        for (int mt = 0; mt < 2; mt++) {
            const uint2* am = a0 + mt * (16 * 128);
            uint2 f0 = __ldg(am + kpo);
            uint2 f1 = __ldg(am + 8 * 128 + kpo);
            uint2 f2 = __ldg(am + kpo + 4);
            uint2 f3 = __ldg(am + 8 * 128 + kpo + 4);
            ah[mt] = make_uint4(f0.x, f1.x, f2.x, f3.x);
            al[mt] = make_uint4(f0.y, f1.y, f2.y, f3.y);
        }
        uint4 bb[8];
#pragma unroll
        for (int nt = 0; nt < 8; nt++)
            bb[nt] = __ldg(bp + nt * 512 + kc * 32);
#pragma unroll
        for (int mt = 0; mt < 2; mt++)
#pragma unroll
            for (int nt = 0; nt < 8; nt++) {
                mma_bf16(acc[mt][nt], ah[mt], bb[nt].x, bb[nt].y);
                mma_bf16(acc[mt][nt], ah[mt], bb[nt].z, bb[nt].w);
                mma_bf16(acc[mt][nt], al[mt], bb[nt].x, bb[nt].y);
            }
    }

    // ---- epilogue 1: store h as half2 ----
#pragma unroll
    for (int mt = 0; mt < 2; mt++) {
        int r = row0 + mt * 16 + lm;
#pragma unroll
        for (int nt = 0; nt < 8; nt++) {
            int kp = ((ntg0 + nt) * 8 + lk * 2) >> 1;
            Hout[(size_t)r * 128 + kp]       = __floats2half2_rn(acc[mt][nt][0], acc[mt][nt][1]);
            Hout[(size_t)(r + 8) * 128 + kp] = __floats2half2_rn(acc[mt][nt][2], acc[mt][nt][3]);
        }
    }

    // ---- epilogue 2: fused alpha (warp's 64 cols = one full head) ----
    int hh = blockIdx.y * 2 + wc;
#pragma unroll
    for (int mt = 0; mt < 2; mt++) {
#pragma unroll
        for (int b = 0; b < 2; b++) {
            float s = 0.f, d = 0.f;
#pragma unroll
            for (int nt = 0; nt < 8; nt++) {
                int c = (ntg0 + nt) * 8 + lk * 2;
                float v0 = acc[mt][nt][2 * b], v1 = acc[mt][nt][2 * b + 1];
                s += v0 * __ldg(&a_s[c]) + v1 * __ldg(&a_s[c + 1]);
                d += v0 * __ldg(&a_d[c]) + v1 * __ldg(&a_d[c + 1]);
            }
            s += __shfl_xor_sync(0xffffffffu, s, 1);
            s += __shfl_xor_sync(0xffffffffu, s, 2);
            d += __shfl_xor_sync(0xffffffffu, d, 1);
            d += __shfl_xor_sync(0xffffffffu, d, 2);
            if (lk == 0) {
                int row = row0 + mt * 16 + lm + 8 * b;
                g_as[row * 4 + hh] = s;
                g_ad[row * 4 + hh] = d;
            }
        }
    }
}

// ---------------- warp-per-node gather (fp16 h); packs output for the next GEMM ----------------
template <bool RELU, bool PACK>
__global__ void k_gather(const __half2* __restrict__ h, const float* __restrict__ bias,
                         float* __restrict__ out) {
    int gw = (blockIdx.x * blockDim.x + threadIdx.x) >> 5;
    int lane = threadIdx.x & 31;
    if (gw >= NN) return;
    int s0 = g_off[gw], s1 = g_off[gw + 1];
    float4 dv = *(const float4*)(g_ad + gw * 4);
    float2 acc[4];
#pragma unroll
    for (int j = 0; j < 4; j++) acc[j] = make_float2(0.f, 0.f);
    float den0 = 0.f, den1 = 0.f, den2 = 0.f, den3 = 0.f;

    for (int i = s0; i < s1; i++) {
        int s = __ldg(&g_csr[i]);
        float4 a = __ldg((const float4*)g_as + s);
        float w0 = __expf(lrelu(a.x + dv.x));
        float w1 = __expf(lrelu(a.y + dv.y));
        float w2 = __expf(lrelu(a.z + dv.z));
        float w3 = __expf(lrelu(a.w + dv.w));
        den0 += w0; den1 += w1; den2 += w2; den3 += w3;
        const __half2* hs = h + (size_t)s * 128;
        float wl[4] = {w0, w1, w2, w3};
#pragma unroll
        for (int j = 0; j < 4; j++) {
            float2 v = __half22float2(__ldg(&hs[lane + 32 * j]));
            acc[j].x += wl[j] * v.x;
            acc[j].y += wl[j] * v.y;
        }
    }
    float4 av = *(const float4*)(g_as + gw * 4);
    float ws[4];
    ws[0] = __expf(lrelu(av.x + dv.x));
    ws[1] = __expf(lrelu(av.y + dv.y));
    ws[2] = __expf(lrelu(av.z + dv.z));
    ws[3] = __expf(lrelu(av.w + dv.w));
    float den[4] = {den0 + ws[0], den1 + ws[1], den2 + ws[2], den3 + ws[3]};
    const __half2* hn = h + (size_t)gw * 128;
    const float2* bias2 = (const float2*)bias;
#pragma unroll
    for (int j = 0; j < 4; j++) {
        int kp = lane + 32 * j;
        float2 hv = __half22float2(__ldg(&hn[kp]));
        float2 bv = __ldg(&bias2[kp]);
        float inv = 1.f / den[j];
        float vx = (acc[j].x + ws[j] * hv.x) * inv + bv.x;
        float vy = (acc[j].y + ws[j] * hv.y) * inv + bv.y;
        if (RELU) { vx = fmaxf(vx, 0.f); vy = fmaxf(vy, 0.f); }
        if (PACK) {
            uint2 o;
            pack_pair(vx, vy, o.x, o.y);
            g_a2[(size_t)gw * 128 + kp] = o;
        } else {
            ((float2*)(out + (size_t)gw * HC))[kp] = make_float2(vx, vy);
        }
    }
}

// ---------------- pooling + MLP head ----------------
__global__ void k_pool(const float* __restrict__ h3) {
    int g = blockIdx.x;
    int c = threadIdx.x;
    int s = g_goff[g], e = g_goff[g + 1];
    float sum = 0.f;
    for (int n = s; n < e; n++) sum += h3[(size_t)n * HC + c];
    float cntf = (float)(e - s);
    g_pooled[g * HC + c] = sum / fmaxf(cntf, 1.0f);
}

__global__ void k_mlp1(const float* __restrict__ Wm1, const float* __restrict__ bm1) {
    __shared__ float sp[HC];
    int g = blockIdx.x;
    int j = threadIdx.x;
    if (j < HC) sp[j] = g_pooled[g * HC + j];
    __syncthreads();
    float acc = __ldg(&bm1[j]);
    for (int k = 0; k < HC; k++) acc += sp[k] * __ldg(&Wm1[(size_t)k * NHID + j]);
    g_hid[g * NHID + j] = fmaxf(acc, 0.f);
}

__global__ void k_mlp2(const float* __restrict__ Wm2, const float* __restrict__ bm2,
                       float* __restrict__ out) {
    __shared__ float sp[NHID];
    int g = blockIdx.x;
    int j = threadIdx.x;
    for (int k = j; k < NHID; k += NOUT) sp[k] = g_hid[g * NHID + k];
    __syncthreads();
    float acc = __ldg(&bm2[j]);
    for (int k = 0; k < NHID; k++) acc += sp[k] * __ldg(&Wm2[(size_t)k * NOUT + j]);
    out[g * NOUT + j] = acc;
}

// ---------------- launch ----------------
extern "C" void kernel_launch(void* const* d_in, const int* in_sizes, int n_in,
                              void* d_out, int out_size) {
    const float* x     = (const float*)d_in[0];
    const void*  ei    = d_in[1];
    const void*  batch = d_in[2];
    const float* W1  = (const float*)d_in[3];
    const float* as1 = (const float*)d_in[4];
    const float* ad1 = (const float*)d_in[5];
    const float* b1  = (const float*)d_in[6];
    const float* W2  = (const float*)d_in[7];
    const float* as2 = (const float*)d_in[8];
    const float* ad2 = (const float*)d_in[9];
    const float* b2  = (const float*)d_in[10];
    const float* W3  = (const float*)d_in[11];
    const float* as3 = (const float*)d_in[12];
    const float* ad3 = (const float*)d_in[13];
    const float* b3  = (const float*)d_in[14];
    const float* Wm1 = (const float*)d_in[15];
    const float* bm1 = (const float*)d_in[16];
    const float* Wm2 = (const float*)d_in[17];
    const float* bm2 = (const float*)d_in[18];
    float* out = (float*)d_out;

    float* bufB;
    __half2* h16;
    uint2* a2;
    uint4 *bf1, *bf2, *bf3;
    cudaGetSymbolAddress((void**)&bufB, g_bufB);
    cudaGetSymbolAddress((void**)&h16, g_h16);
    cudaGetSymbolAddress((void**)&a2, g_a2);
    cudaGetSymbolAddress((void**)&bf1, g_bf1);
    cudaGetSymbolAddress((void**)&bf2, g_bf2);
    cudaGetSymbolAddress((void**)&bf3, g_bf3);

    const int TPB = 256;
    int nb_node = (NN + TPB - 1) / TPB;     // 157
    int nb_edge = (EE + TPB - 1) / TPB;
    int nb_warp = (NN * 32 + TPB - 1) / TPB;
    int nb_split = (NN * 128 + TPB - 1) / TPB;

    dim3 gemm_grid(NN / 64, 2);

    // launch index 3 (0-based) is what ncu captures -> keep gemm there
    k_detect<<<1, 32>>>(ei, batch);                              // 0
    k_prep<<<nb_node, TPB>>>(W1, W2, W3);                        // 1
    k_split<<<nb_split, TPB>>>(x);                               // 2
    k_gemm_bf<<<gemm_grid, 128>>>(a2, bf1, as1, ad1, h16);       // 3  <- profiled
    k_count<<<nb_edge, TPB>>>(ei);                               // 4
    k_gbounds<<<1, 128>>>(batch);                                // 5
    k_scan1<<<nb_node, TPB>>>();                                 // 6
    k_scan2<<<1, 256>>>(nb_node);                                // 7
    k_scan3<<<nb_node, TPB>>>();                                 // 8
    k_fill<<<nb_edge, TPB>>>(ei);                                // 9

    // Layer 1 (gemm + alpha already done)
    k_gather<true, true><<<nb_warp, TPB>>>(h16, b1, bufB);

    // Layer 2
    k_gemm_bf<<<gemm_grid, 128>>>(a2, bf2, as2, ad2, h16);
    k_gather<true, true><<<nb_warp, TPB>>>(h16, b2, bufB);

    // Layer 3 (no relu, fp32 out for pooling)
    k_gemm_bf<<<gemm_grid, 128>>>(a2, bf3, as3, ad3, h16);
    k_gather<false, false><<<nb_warp, TPB>>>(h16, b3, bufB);

    // Pool + MLP
    k_pool<<<GG, HC>>>(bufB);
    k_mlp1<<<GG, NHID>>>(Wm1, bm1);
    k_mlp2<<<GG, NOUT>>>(Wm2, bm2, out);
}

// round 8
// speedup vs baseline: 2.1749x; 1.3079x over previous
#include <cuda_runtime.h>
#include <cuda_bf16.h>
#include <cuda_fp16.h>
#include <math.h>
#include <stdint.h>

#define NN   40000
#define EE   640000
#define GG   64
#define HH   4
#define CC   64
#define HC   256
#define NHID 1024
#define NOUT 768
#define NEG_SLOPE 0.2f

// ---------------- static device scratch ----------------
__device__ __half2 g_h16[(size_t)NN * 128];      // gemm output h (fp16 pairs) for gather
__device__ float g_bufB[(size_t)NN * HC];        // layer-3 gather output (fp32)
__device__ uint2 g_a2[(size_t)NN * 128];         // packed gemm input: (bf162 hi, bf162 lo) per k-pair
__device__ float g_as[NN * 4];
__device__ float g_ad[NN * 4];
__device__ int   g_cnt[NN];
__device__ int   g_cur[NN];
__device__ int   g_off[NN + 1];
__device__ int   g_csr[EE];
__device__ int   g_goff[GG + 1];
__device__ float g_pooled[GG * HC];
__device__ float g_hid[GG * NHID];
__device__ int   g_is64_e, g_is64_b;
__device__ int   g_bsum[160];
__device__ int   g_boff[160];
// B in mma-fragment order: idx = (ntg*16 + kc)*32 + lane, uint4 = {bh0, bh1, bl0, bl1}
__device__ uint4 g_bf1[16384], g_bf2[16384], g_bf3[16384];

__device__ __forceinline__ float lrelu(float v) {
    return v > 0.f ? v : NEG_SLOPE * v;
}

__device__ __forceinline__ int idx_at(const void* p, long long i, int is64) {
    if (is64) return (int)((const long long*)p)[i];
    return ((const int*)p)[i];
}

__device__ __forceinline__ void pack_pair(float a, float b, unsigned& hi, unsigned& lo) {
    __nv_bfloat16 ha = __float2bfloat16(a);
    __nv_bfloat16 hb = __float2bfloat16(b);
    float la = a - __bfloat162float(ha);
    float lb = b - __bfloat162float(hb);
    __nv_bfloat162 hp = __halves2bfloat162(ha, hb);
    __nv_bfloat162 lp = __halves2bfloat162(__float2bfloat16(la), __float2bfloat16(lb));
    hi = *(unsigned*)&hp;
    lo = *(unsigned*)&lp;
}

// ---------------- prep: detect dtypes + zero counters + weight fragments + split x ----------------
__global__ void k_prep(const float* __restrict__ x,
                       const float* __restrict__ W1, const float* __restrict__ W2,
                       const float* __restrict__ W3,
                       const void* ei, const void* batch) {
    int i = blockIdx.x * blockDim.x + threadIdx.x;

    // dtype detection (block 0, warp 0): int64 LE non-negative => odd 32-bit words all zero
    if (blockIdx.x == 0 && threadIdx.x < 32) {
        int lane = threadIdx.x;
        const int* e32 = (const int*)ei;
        int nz = 0;
        for (int j = lane; j < 64; j += 32) nz |= (e32[2 * j + 1] != 0);
        nz = __any_sync(0xffffffffu, nz);
        if (lane == 0) g_is64_e = !nz;
        const int* b32 = (const int*)batch;
        int nzb = (b32[NN - 1 - 2 * lane] != 0);   // odd word indices in the tail
        nzb = __any_sync(0xffffffffu, nzb);
        if (lane == 0) g_is64_b = !nzb;
    }

    if (i < NN) { g_cnt[i] = 0; g_cur[i] = 0; }

    if (i < 16384) {
        int ntg = i >> 9;
        int kc  = (i >> 5) & 15;
        int lane = i & 31;
        int lm = lane >> 2, lk = lane & 3;
        int n = ntg * 8 + lm;
        int k0 = kc * 16 + 2 * lk;
        uint4 f;
        {
            pack_pair(W1[(size_t)k0 * 256 + n], W1[(size_t)(k0 + 1) * 256 + n], f.x, f.z);
            pack_pair(W1[(size_t)(k0 + 8) * 256 + n], W1[(size_t)(k0 + 9) * 256 + n], f.y, f.w);
            g_bf1[i] = f;
        }
        {
            pack_pair(W2[(size_t)k0 * 256 + n], W2[(size_t)(k0 + 1) * 256 + n], f.x, f.z);
            pack_pair(W2[(size_t)(k0 + 8) * 256 + n], W2[(size_t)(k0 + 9) * 256 + n], f.y, f.w);
            g_bf2[i] = f;
        }
        {
            pack_pair(W3[(size_t)k0 * 256 + n], W3[(size_t)(k0 + 1) * 256 + n], f.x, f.z);
            pack_pair(W3[(size_t)(k0 + 8) * 256 + n], W3[(size_t)(k0 + 9) * 256 + n], f.y, f.w);
            g_bf3[i] = f;
        }
    }

    // split x into packed A2
    if (i < NN * 128) {
        float2 v = ((const float2*)x)[i];
        uint2 o;
        pack_pair(v.x, v.y, o.x, o.y);
        g_a2[i] = o;
    }
}

// ---------------- CSR ----------------
__global__ void k_count(const void* __restrict__ ei) {
    int e = blockIdx.x * blockDim.x + threadIdx.x;
    if (e < EE) atomicAdd(&g_cnt[idx_at(ei, (long long)EE + e, g_is64_e)], 1);
}

__global__ void k_gbounds(const void* __restrict__ batch) {
    int g = threadIdx.x;
    if (g > GG) return;
    int is64 = g_is64_b;
    int lo = 0, hi = NN;
    while (lo < hi) {
        int mid = (lo + hi) >> 1;
        if (idx_at(batch, mid, is64) < g) lo = mid + 1; else hi = mid;
    }
    g_goff[g] = lo;
}

__global__ void k_scan1() {
    __shared__ int sd[256];
    int b = blockIdx.x, t = threadIdx.x;
    int i = b * 256 + t;
    int v = (i < NN) ? g_cnt[i] : 0;
    sd[t] = v;
    __syncthreads();
#pragma unroll
    for (int o = 1; o < 256; o <<= 1) {
        int y = (t >= o) ? sd[t - o] : 0;
        __syncthreads();
        sd[t] += y;
        __syncthreads();
    }
    if (i < NN) g_off[i] = sd[t] - v;
    if (t == 255) g_bsum[b] = sd[255];
}

__global__ void k_scan2(int nb) {
    __shared__ int sd[256];
    int t = threadIdx.x;
    int v = (t < nb) ? g_bsum[t] : 0;
    sd[t] = v;
    __syncthreads();
#pragma unroll
    for (int o = 1; o < 256; o <<= 1) {
        int y = (t >= o) ? sd[t - o] : 0;
        __syncthreads();
        sd[t] += y;
        __syncthreads();
    }
    if (t < nb) g_boff[t] = sd[t] - v;
    if (t == 0) g_off[NN] = EE;
}

__global__ void k_scan3() {
    int i = blockIdx.x * blockDim.x + threadIdx.x;
    if (i < NN) g_off[i] += g_boff[blockIdx.x];
}

__global__ void k_fill(const void* __restrict__ ei) {
    int e = blockIdx.x * blockDim.x + threadIdx.x;
    if (e >= EE) return;
    int is64 = g_is64_e;
    int s = idx_at(ei, e, is64);
    int d = idx_at(ei, (long long)EE + e, is64);
    int pos = atomicAdd(&g_cur[d], 1);
    g_csr[g_off[d] + pos] = s;
}

// ---------------- smem-free bf16 3-term tensor-core GEMM + fused alpha + fp16 h out ----------------
__device__ __forceinline__ void mma_bf16(float* d, const uint4& a, unsigned b0, unsigned b1) {
    asm volatile(
        "mma.sync.aligned.m16n8k16.row.col.f32.bf16.bf16.f32 "
        "{%0,%1,%2,%3}, {%4,%5,%6,%7}, {%8,%9}, {%0,%1,%2,%3};\n"
        : "+f"(d[0]), "+f"(d[1]), "+f"(d[2]), "+f"(d[3])
        : "r"(a.x), "r"(a.y), "r"(a.z), "r"(a.w), "r"(b0), "r"(b1));
}

__global__ void __launch_bounds__(128, 3) k_gemm_bf(const uint2* __restrict__ A2,
                                                    const uint4* __restrict__ Bf,
                                                    const float* __restrict__ a_s,
                                                    const float* __restrict__ a_d,
                                                    __half2* __restrict__ Hout) {
    int tid = threadIdx.x;
    int warp = tid >> 5, lane = tid & 31;
    int lm = lane >> 2, lk = lane & 3;
    int wm = warp & 1, wc = warp >> 1;
    int row0 = blockIdx.x * 64 + wm * 32;
    int ntg0 = blockIdx.y * 16 + wc * 8;

    float acc[2][8][4];
#pragma unroll
    for (int mt = 0; mt < 2; mt++)
#pragma unroll
        for (int nt = 0; nt < 8; nt++)
#pragma unroll
            for (int r = 0; r < 4; r++) acc[mt][nt][r] = 0.f;

    const uint2* a0 = A2 + (size_t)(row0 + lm) * 128 + lk;
    const uint4* bp = Bf + ntg0 * 512 + lane;

#pragma unroll
    for (int kc = 0; kc < 16; kc++) {
        int kpo = kc * 8;
        uint4 ah[2], al[2];
#pragma unroll
        for (int mt = 0; mt < 2; mt++) {
            const uint2* am = a0 + mt * (16 * 128);
            uint2 f0 = __ldg(am + kpo);
            uint2 f1 = __ldg(am + 8 * 128 + kpo);
            uint2 f2 = __ldg(am + kpo + 4);
            uint2 f3 = __ldg(am + 8 * 128 + kpo + 4);
            ah[mt] = make_uint4(f0.x, f1.x, f2.x, f3.x);
            al[mt] = make_uint4(f0.y, f1.y, f2.y, f3.y);
        }
        uint4 bb[8];
#pragma unroll
        for (int nt = 0; nt < 8; nt++)
            bb[nt] = __ldg(bp + nt * 512 + kc * 32);
#pragma unroll
        for (int mt = 0; mt < 2; mt++)
#pragma unroll
            for (int nt = 0; nt < 8; nt++) {
                mma_bf16(acc[mt][nt], ah[mt], bb[nt].x, bb[nt].y);
                mma_bf16(acc[mt][nt], ah[mt], bb[nt].z, bb[nt].w);
                mma_bf16(acc[mt][nt], al[mt], bb[nt].x, bb[nt].y);
            }
    }

    // ---- epilogue 1: store h as half2 ----
#pragma unroll
    for (int mt = 0; mt < 2; mt++) {
        int r = row0 + mt * 16 + lm;
#pragma unroll
        for (int nt = 0; nt < 8; nt++) {
            int kp = ((ntg0 + nt) * 8 + lk * 2) >> 1;
            Hout[(size_t)r * 128 + kp]       = __floats2half2_rn(acc[mt][nt][0], acc[mt][nt][1]);
            Hout[(size_t)(r + 8) * 128 + kp] = __floats2half2_rn(acc[mt][nt][2], acc[mt][nt][3]);
        }
    }

    // ---- epilogue 2: fused alpha (warp's 64 cols = one full head) ----
    int hh = blockIdx.y * 2 + wc;
#pragma unroll
    for (int mt = 0; mt < 2; mt++) {
#pragma unroll
        for (int b = 0; b < 2; b++) {
            float s = 0.f, d = 0.f;
#pragma unroll
            for (int nt = 0; nt < 8; nt++) {
                int c = (ntg0 + nt) * 8 + lk * 2;
                float v0 = acc[mt][nt][2 * b], v1 = acc[mt][nt][2 * b + 1];
                s += v0 * __ldg(&a_s[c]) + v1 * __ldg(&a_s[c + 1]);
                d += v0 * __ldg(&a_d[c]) + v1 * __ldg(&a_d[c + 1]);
            }
            s += __shfl_xor_sync(0xffffffffu, s, 1);
            s += __shfl_xor_sync(0xffffffffu, s, 2);
            d += __shfl_xor_sync(0xffffffffu, d, 1);
            d += __shfl_xor_sync(0xffffffffu, d, 2);
            if (lk == 0) {
                int row = row0 + mt * 16 + lm + 8 * b;
                g_as[row * 4 + hh] = s;
                g_ad[row * 4 + hh] = d;
            }
        }
    }
}

// ---------------- warp-per-node gather: lane owns cols [8l, 8l+8), head q = l>>3 ----------------
// Per edge: 1 LDG.32 (csr, broadcast) + 1 LDG.32 (alpha_src scalar) + 1 LDG.128 (h row chunk),
// 1 exp. Lanes within a head-group hold identical denominators (no reduction needed).
template <bool RELU, bool PACK>
__global__ void k_gather(const __half2* __restrict__ h, const float* __restrict__ bias,
                         float* __restrict__ out) {
    int gw = (blockIdx.x * blockDim.x + threadIdx.x) >> 5;
    int lane = threadIdx.x & 31;
    if (gw >= NN) return;
    int q = lane >> 3;                       // head of this lane's 8 columns
    int s0 = g_off[gw], s1 = g_off[gw + 1];
    float dvq = __ldg(&g_ad[gw * 4 + q]);

    float acc[8];
#pragma unroll
    for (int j = 0; j < 8; j++) acc[j] = 0.f;
    float den = 0.f;

    const uint4* hb = (const uint4*)h;       // row = 32 uint4 (512 B)
    for (int i = s0; i < s1; i++) {
        int s = __ldg(&g_csr[i]);
        float aq = __ldg(&g_as[s * 4 + q]);
        float w = __expf(lrelu(aq + dvq));
        den += w;
        uint4 v = __ldg(hb + (size_t)s * 32 + lane);
        float2 f0 = __half22float2(*(__half2*)&v.x);
        float2 f1 = __half22float2(*(__half2*)&v.y);
        float2 f2 = __half22float2(*(__half2*)&v.z);
        float2 f3 = __half22float2(*(__half2*)&v.w);
        acc[0] += w * f0.x; acc[1] += w * f0.y;
        acc[2] += w * f1.x; acc[3] += w * f1.y;
        acc[4] += w * f2.x; acc[5] += w * f2.y;
        acc[6] += w * f3.x; acc[7] += w * f3.y;
    }
    // self loop
    float asq = __ldg(&g_as[gw * 4 + q]);
    float wsl = __expf(lrelu(asq + dvq));
    den += wsl;
    uint4 hv = __ldg(hb + (size_t)gw * 32 + lane);
    float2 h0 = __half22float2(*(__half2*)&hv.x);
    float2 h1 = __half22float2(*(__half2*)&hv.y);
    float2 h2 = __half22float2(*(__half2*)&hv.z);
    float2 h3 = __half22float2(*(__half2*)&hv.w);
    float hf[8] = {h0.x, h0.y, h1.x, h1.y, h2.x, h2.y, h3.x, h3.y};

    float4 b0 = __ldg((const float4*)bias + lane * 2);
    float4 b1 = __ldg((const float4*)bias + lane * 2 + 1);
    float bf[8] = {b0.x, b0.y, b0.z, b0.w, b1.x, b1.y, b1.z, b1.w};

    float inv = 1.f / den;
    float vv[8];
#pragma unroll
    for (int j = 0; j < 8; j++) {
        float v = (acc[j] + wsl * hf[j]) * inv + bf[j];
        if (RELU) v = fmaxf(v, 0.f);
        vv[j] = v;
    }
    if (PACK) {
        uint2 o0, o1, o2, o3;
        pack_pair(vv[0], vv[1], o0.x, o0.y);
        pack_pair(vv[2], vv[3], o1.x, o1.y);
        pack_pair(vv[4], vv[5], o2.x, o2.y);
        pack_pair(vv[6], vv[7], o3.x, o3.y);
        uint4* dst = (uint4*)&g_a2[(size_t)gw * 128 + lane * 4];
        dst[0] = make_uint4(o0.x, o0.y, o1.x, o1.y);
        dst[1] = make_uint4(o2.x, o2.y, o3.x, o3.y);
    } else {
        float4* dst = (float4*)(out + (size_t)gw * HC + lane * 8);
        dst[0] = make_float4(vv[0], vv[1], vv[2], vv[3]);
        dst[1] = make_float4(vv[4], vv[5], vv[6], vv[7]);
    }
}

// ---------------- pooling + MLP head ----------------
__global__ void k_pool(const float* __restrict__ h3) {
    int g = blockIdx.x;
    int c = threadIdx.x;
    int s = g_goff[g], e = g_goff[g + 1];
    float sum = 0.f;
    for (int n = s; n < e; n++) sum += h3[(size_t)n * HC + c];
    float cntf = (float)(e - s);
    g_pooled[g * HC + c] = sum / fmaxf(cntf, 1.0f);
}

__global__ void k_mlp1(const float* __restrict__ Wm1, const float* __restrict__ bm1) {
    __shared__ float sp[HC];
    int g = blockIdx.x;
    int j = threadIdx.x;
    if (j < HC) sp[j] = g_pooled[g * HC + j];
    __syncthreads();
    float acc = __ldg(&bm1[j]);
    for (int k = 0; k < HC; k++) acc += sp[k] * __ldg(&Wm1[(size_t)k * NHID + j]);
    g_hid[g * NHID + j] = fmaxf(acc, 0.f);
}

__global__ void k_mlp2(const float* __restrict__ Wm2, const float* __restrict__ bm2,
                       float* __restrict__ out) {
    __shared__ float sp[NHID];
    int g = blockIdx.x;
    int j = threadIdx.x;
    for (int k = j; k < NHID; k += NOUT) sp[k] = g_hid[g * NHID + k];
    __syncthreads();
    float acc = __ldg(&bm2[j]);
    for (int k = 0; k < NHID; k++) acc += sp[k] * __ldg(&Wm2[(size_t)k * NOUT + j]);
    out[g * NOUT + j] = acc;
}

// ---------------- launch ----------------
extern "C" void kernel_launch(void* const* d_in, const int* in_sizes, int n_in,
                              void* d_out, int out_size) {
    const float* x     = (const float*)d_in[0];
    const void*  ei    = d_in[1];
    const void*  batch = d_in[2];
    const float* W1  = (const float*)d_in[3];
    const float* as1 = (const float*)d_in[4];
    const float* ad1 = (const float*)d_in[5];
    const float* b1  = (const float*)d_in[6];
    const float* W2  = (const float*)d_in[7];
    const float* as2 = (const float*)d_in[8];
    const float* ad2 = (const float*)d_in[9];
    const float* b2  = (const float*)d_in[10];
    const float* W3  = (const float*)d_in[11];
    const float* as3 = (const float*)d_in[12];
    const float* ad3 = (const float*)d_in[13];
    const float* b3  = (const float*)d_in[14];
    const float* Wm1 = (const float*)d_in[15];
    const float* bm1 = (const float*)d_in[16];
    const float* Wm2 = (const float*)d_in[17];
    const float* bm2 = (const float*)d_in[18];
    float* out = (float*)d_out;

    float* bufB;
    __half2* h16;
    uint2* a2;
    uint4 *bf1, *bf2, *bf3;
    cudaGetSymbolAddress((void**)&bufB, g_bufB);
    cudaGetSymbolAddress((void**)&h16, g_h16);
    cudaGetSymbolAddress((void**)&a2, g_a2);
    cudaGetSymbolAddress((void**)&bf1, g_bf1);
    cudaGetSymbolAddress((void**)&bf2, g_bf2);
    cudaGetSymbolAddress((void**)&bf3, g_bf3);

    const int TPB = 256;
    int nb_node = (NN + TPB - 1) / TPB;          // 157
    int nb_edge = (EE + TPB - 1) / TPB;
    int nb_warp = (NN * 32 + TPB - 1) / TPB;
    int nb_prep = (NN * 128 + TPB - 1) / TPB;    // covers split + weights + zero

    dim3 gemm_grid(NN / 64, 2);

    // launch index 3 (0-based) is what ncu captures -> keep gemm there
    k_prep<<<nb_prep, TPB>>>(x, W1, W2, W3, ei, batch);          // 0 (detect+zero+weights+split)
    k_count<<<nb_edge, TPB>>>(ei);                               // 1
    k_scan1<<<nb_node, TPB>>>();                                 // 2
    k_gemm_bf<<<gemm_grid, 128>>>(a2, bf1, as1, ad1, h16);       // 3  <- profiled
    k_scan2<<<1, 256>>>(nb_node);                                // 4
    k_scan3<<<nb_node, TPB>>>();                                 // 5
    k_fill<<<nb_edge, TPB>>>(ei);                                // 6
    k_gbounds<<<1, 128>>>(batch);                                // 7

    // Layer 1 (gemm + alpha already done)
    k_gather<true, true><<<nb_warp, TPB>>>(h16, b1, bufB);

    // Layer 2
    k_gemm_bf<<<gemm_grid, 128>>>(a2, bf2, as2, ad2, h16);
    k_gather<true, true><<<nb_warp, TPB>>>(h16, b2, bufB);

    // Layer 3 (no relu, fp32 out for pooling)
    k_gemm_bf<<<gemm_grid, 128>>>(a2, bf3, as3, ad3, h16);
    k_gather<false, false><<<nb_warp, TPB>>>(h16, b3, bufB);

    // Pool + MLP
    k_pool<<<GG, HC>>>(bufB);
    k_mlp1<<<GG, NHID>>>(Wm1, bm1);
    k_mlp2<<<GG, NOUT>>>(Wm2, bm2, out);
}

// round 9
// speedup vs baseline: 2.3592x; 1.0847x over previous
#include <cuda_runtime.h>
#include <cuda_fp16.h>
#include <math.h>
#include <stdint.h>

#define NN   40000
#define EE   640000
#define GG   64
#define HH   4
#define CC   64
#define HC   256
#define NHID 1024
#define NOUT 768
#define NEG_SLOPE 0.2f

// ---------------- static device scratch ----------------
__device__ __half2 g_h16[(size_t)NN * 128];      // gemm output h (fp16 pairs) for gather
__device__ float g_bufB[(size_t)NN * HC];        // layer-3 gather output (fp32)
__device__ unsigned g_a2[(size_t)NN * 128];      // gemm input: fp16 pair per k-pair
__device__ float g_as[NN * 4];
__device__ float g_ad[NN * 4];
__device__ int   g_cnt[NN];
__device__ int   g_cur[NN];
__device__ int   g_off[NN + 1];
__device__ int   g_csr[EE];
__device__ int   g_goff[GG + 1];
__device__ float g_pooled[GG * HC];
__device__ float g_hid[GG * NHID];
__device__ int   g_is64_e, g_is64_b;
__device__ int   g_bsum[160];
__device__ int   g_boff[160];
// B in mma-fragment order: idx = (ntg*16 + kc)*32 + lane, uint2 = {b0, b1} fp16x2
__device__ uint2 g_bf1[16384], g_bf2[16384], g_bf3[16384];

__device__ __forceinline__ float lrelu(float v) {
    return v > 0.f ? v : NEG_SLOPE * v;
}

__device__ __forceinline__ int idx_at(const void* p, long long i, int is64) {
    if (is64) return (int)((const long long*)p)[i];
    return ((const int*)p)[i];
}

__device__ __forceinline__ unsigned h2u(__half2 h) { return *(unsigned*)&h; }

// ---------------- prep: detect dtypes + zero counters + weight fragments + split x ----------------
__global__ void k_prep(const float* __restrict__ x,
                       const float* __restrict__ W1, const float* __restrict__ W2,
                       const float* __restrict__ W3,
                       const void* ei, const void* batch) {
    int i = blockIdx.x * blockDim.x + threadIdx.x;

    // dtype detection (block 0, warp 0): int64 LE non-negative => odd 32-bit words all zero
    if (blockIdx.x == 0 && threadIdx.x < 32) {
        int lane = threadIdx.x;
        const int* e32 = (const int*)ei;
        int nz = 0;
        for (int j = lane; j < 64; j += 32) nz |= (e32[2 * j + 1] != 0);
        nz = __any_sync(0xffffffffu, nz);
        if (lane == 0) g_is64_e = !nz;
        const int* b32 = (const int*)batch;
        int nzb = (b32[NN - 1 - 2 * lane] != 0);
        nzb = __any_sync(0xffffffffu, nzb);
        if (lane == 0) g_is64_b = !nzb;
    }

    if (i < NN) { g_cnt[i] = 0; g_cur[i] = 0; }

    if (i < 16384) {
        int ntg = i >> 9;
        int kc  = (i >> 5) & 15;
        int lane = i & 31;
        int lm = lane >> 2, lk = lane & 3;
        int n = ntg * 8 + lm;
        int k0 = kc * 16 + 2 * lk;
        uint2 f;
        f.x = h2u(__floats2half2_rn(W1[(size_t)k0 * 256 + n], W1[(size_t)(k0 + 1) * 256 + n]));
        f.y = h2u(__floats2half2_rn(W1[(size_t)(k0 + 8) * 256 + n], W1[(size_t)(k0 + 9) * 256 + n]));
        g_bf1[i] = f;
        f.x = h2u(__floats2half2_rn(W2[(size_t)k0 * 256 + n], W2[(size_t)(k0 + 1) * 256 + n]));
        f.y = h2u(__floats2half2_rn(W2[(size_t)(k0 + 8) * 256 + n], W2[(size_t)(k0 + 9) * 256 + n]));
        g_bf2[i] = f;
        f.x = h2u(__floats2half2_rn(W3[(size_t)k0 * 256 + n], W3[(size_t)(k0 + 1) * 256 + n]));
        f.y = h2u(__floats2half2_rn(W3[(size_t)(k0 + 8) * 256 + n], W3[(size_t)(k0 + 9) * 256 + n]));
        g_bf3[i] = f;
    }

    // split x into fp16 A2
    if (i < NN * 128) {
        float2 v = ((const float2*)x)[i];
        g_a2[i] = h2u(__floats2half2_rn(v.x, v.y));
    }
}

// ---------------- CSR ----------------
__global__ void k_count(const void* __restrict__ ei) {
    int e = blockIdx.x * blockDim.x + threadIdx.x;
    if (e < EE) atomicAdd(&g_cnt[idx_at(ei, (long long)EE + e, g_is64_e)], 1);
}

__global__ void k_gbounds(const void* __restrict__ batch) {
    int g = threadIdx.x;
    if (g > GG) return;
    int is64 = g_is64_b;
    int lo = 0, hi = NN;
    while (lo < hi) {
        int mid = (lo + hi) >> 1;
        if (idx_at(batch, mid, is64) < g) lo = mid + 1; else hi = mid;
    }
    g_goff[g] = lo;
}

__global__ void k_scan1() {
    __shared__ int sd[256];
    int b = blockIdx.x, t = threadIdx.x;
    int i = b * 256 + t;
    int v = (i < NN) ? g_cnt[i] : 0;
    sd[t] = v;
    __syncthreads();
#pragma unroll
    for (int o = 1; o < 256; o <<= 1) {
        int y = (t >= o) ? sd[t - o] : 0;
        __syncthreads();
        sd[t] += y;
        __syncthreads();
    }
    if (i < NN) g_off[i] = sd[t] - v;
    if (t == 255) g_bsum[b] = sd[255];
}

__global__ void k_scan2(int nb) {
    __shared__ int sd[256];
    int t = threadIdx.x;
    int v = (t < nb) ? g_bsum[t] : 0;
    sd[t] = v;
    __syncthreads();
#pragma unroll
    for (int o = 1; o < 256; o <<= 1) {
        int y = (t >= o) ? sd[t - o] : 0;
        __syncthreads();
        sd[t] += y;
        __syncthreads();
    }
    if (t < nb) g_boff[t] = sd[t] - v;
    if (t == 0) g_off[NN] = EE;
}

__global__ void k_scan3() {
    int i = blockIdx.x * blockDim.x + threadIdx.x;
    if (i < NN) g_off[i] += g_boff[blockIdx.x];
}

__global__ void k_fill(const void* __restrict__ ei) {
    int e = blockIdx.x * blockDim.x + threadIdx.x;
    if (e >= EE) return;
    int is64 = g_is64_e;
    int s = idx_at(ei, e, is64);
    int d = idx_at(ei, (long long)EE + e, is64);
    int pos = atomicAdd(&g_cur[d], 1);
    g_csr[g_off[d] + pos] = s;
}

// ---------------- smem-free fp16 single-pass tensor-core GEMM + fused alpha + fp16 h out ----------------
// h[M,256] = A[M,256] @ B[256,256]; fp16 inputs, fp32 accumulate.
// Block: 64x128 tile, 128 threads (4 warps, 2m x 2n), warp tile 32x64 = one full head.

__device__ __forceinline__ void mma_f16(float* d, unsigned a0, unsigned a1, unsigned a2,
                                        unsigned a3, unsigned b0, unsigned b1) {
    asm volatile(
        "mma.sync.aligned.m16n8k16.row.col.f32.f16.f16.f32 "
        "{%0,%1,%2,%3}, {%4,%5,%6,%7}, {%8,%9}, {%0,%1,%2,%3};\n"
        : "+f"(d[0]), "+f"(d[1]), "+f"(d[2]), "+f"(d[3])
        : "r"(a0), "r"(a1), "r"(a2), "r"(a3), "r"(b0), "r"(b1));
}

__global__ void __launch_bounds__(128, 4) k_gemm(const unsigned* __restrict__ A2,
                                                 const uint2* __restrict__ Bf,
                                                 const float* __restrict__ a_s,
                                                 const float* __restrict__ a_d,
                                                 __half2* __restrict__ Hout) {
    int tid = threadIdx.x;
    int warp = tid >> 5, lane = tid & 31;
    int lm = lane >> 2, lk = lane & 3;
    int wm = warp & 1, wc = warp >> 1;
    int row0 = blockIdx.x * 64 + wm * 32;
    int ntg0 = blockIdx.y * 16 + wc * 8;

    float acc[2][8][4];
#pragma unroll
    for (int mt = 0; mt < 2; mt++)
#pragma unroll
        for (int nt = 0; nt < 8; nt++)
#pragma unroll
            for (int r = 0; r < 4; r++) acc[mt][nt][r] = 0.f;

    const unsigned* a0p = A2 + (size_t)(row0 + lm) * 128 + lk;
    const uint2* bp = Bf + ntg0 * 512 + lane;

#pragma unroll
    for (int kc = 0; kc < 16; kc++) {
        int kpo = kc * 8;
        unsigned af[2][4];
#pragma unroll
        for (int mt = 0; mt < 2; mt++) {
            const unsigned* am = a0p + mt * (16 * 128);
            af[mt][0] = __ldg(am + kpo);
            af[mt][1] = __ldg(am + 8 * 128 + kpo);
            af[mt][2] = __ldg(am + kpo + 4);
            af[mt][3] = __ldg(am + 8 * 128 + kpo + 4);
        }
        uint2 bb[8];
#pragma unroll
        for (int nt = 0; nt < 8; nt++)
            bb[nt] = __ldg(bp + nt * 512 + kc * 32);
#pragma unroll
        for (int mt = 0; mt < 2; mt++)
#pragma unroll
            for (int nt = 0; nt < 8; nt++)
                mma_f16(acc[mt][nt], af[mt][0], af[mt][1], af[mt][2], af[mt][3],
                        bb[nt].x, bb[nt].y);
    }

    // ---- epilogue 1: store h as half2 ----
#pragma unroll
    for (int mt = 0; mt < 2; mt++) {
        int r = row0 + mt * 16 + lm;
#pragma unroll
        for (int nt = 0; nt < 8; nt++) {
            int kp = ((ntg0 + nt) * 8 + lk * 2) >> 1;
            Hout[(size_t)r * 128 + kp]       = __floats2half2_rn(acc[mt][nt][0], acc[mt][nt][1]);
            Hout[(size_t)(r + 8) * 128 + kp] = __floats2half2_rn(acc[mt][nt][2], acc[mt][nt][3]);
        }
    }

    // ---- epilogue 2: fused alpha (warp's 64 cols = one full head) ----
    int hh = blockIdx.y * 2 + wc;
#pragma unroll
    for (int mt = 0; mt < 2; mt++) {
#pragma unroll
        for (int b = 0; b < 2; b++) {
            float s = 0.f, d = 0.f;
#pragma unroll
            for (int nt = 0; nt < 8; nt++) {
                int c = (ntg0 + nt) * 8 + lk * 2;
                float v0 = acc[mt][nt][2 * b], v1 = acc[mt][nt][2 * b + 1];
                s += v0 * __ldg(&a_s[c]) + v1 * __ldg(&a_s[c + 1]);
                d += v0 * __ldg(&a_d[c]) + v1 * __ldg(&a_d[c + 1]);
            }
            s += __shfl_xor_sync(0xffffffffu, s, 1);
            s += __shfl_xor_sync(0xffffffffu, s, 2);
            d += __shfl_xor_sync(0xffffffffu, d, 1);
            d += __shfl_xor_sync(0xffffffffu, d, 2);
            if (lk == 0) {
                int row = row0 + mt * 16 + lm + 8 * b;
                g_as[row * 4 + hh] = s;
                g_ad[row * 4 + hh] = d;
            }
        }
    }
}

// ---------------- warp-per-node gather: lane owns cols [8l, 8l+8), head q = l>>3 ----------------
template <bool RELU, bool PACK>
__global__ void k_gather(const __half2* __restrict__ h, const float* __restrict__ bias,
                         float* __restrict__ out) {
    int gw = (blockIdx.x * blockDim.x + threadIdx.x) >> 5;
    int lane = threadIdx.x & 31;
    if (gw >= NN) return;
    int q = lane >> 3;
    int s0 = g_off[gw], s1 = g_off[gw + 1];
    float dvq = __ldg(&g_ad[gw * 4 + q]);

    float acc[8];
#pragma unroll
    for (int j = 0; j < 8; j++) acc[j] = 0.f;
    float den = 0.f;

    const uint4* hb = (const uint4*)h;
    int snext = (s0 < s1) ? __ldg(&g_csr[s0]) : 0;
    for (int i = s0; i < s1; i++) {
        int s = snext;
        if (i + 1 < s1) snext = __ldg(&g_csr[i + 1]);
        float aq = __ldg(&g_as[s * 4 + q]);
        float w = __expf(lrelu(aq + dvq));
        den += w;
        uint4 v = __ldg(hb + (size_t)s * 32 + lane);
        float2 f0 = __half22float2(*(__half2*)&v.x);
        float2 f1 = __half22float2(*(__half2*)&v.y);
        float2 f2 = __half22float2(*(__half2*)&v.z);
        float2 f3 = __half22float2(*(__half2*)&v.w);
        acc[0] += w * f0.x; acc[1] += w * f0.y;
        acc[2] += w * f1.x; acc[3] += w * f1.y;
        acc[4] += w * f2.x; acc[5] += w * f2.y;
        acc[6] += w * f3.x; acc[7] += w * f3.y;
    }
    // self loop
    float asq = __ldg(&g_as[gw * 4 + q]);
    float wsl = __expf(lrelu(asq + dvq));
    den += wsl;
    uint4 hv = __ldg(hb + (size_t)gw * 32 + lane);
    float2 h0 = __half22float2(*(__half2*)&hv.x);
    float2 h1 = __half22float2(*(__half2*)&hv.y);
    float2 h2 = __half22float2(*(__half2*)&hv.z);
    float2 h3 = __half22float2(*(__half2*)&hv.w);
    float hf[8] = {h0.x, h0.y, h1.x, h1.y, h2.x, h2.y, h3.x, h3.y};

    float4 b0 = __ldg((const float4*)bias + lane * 2);
    float4 b1 = __ldg((const float4*)bias + lane * 2 + 1);
    float bf[8] = {b0.x, b0.y, b0.z, b0.w, b1.x, b1.y, b1.z, b1.w};

    float inv = 1.f / den;
    float vv[8];
#pragma unroll
    for (int j = 0; j < 8; j++) {
        float v = (acc[j] + wsl * hf[j]) * inv + bf[j];
        if (RELU) v = fmaxf(v, 0.f);
        vv[j] = v;
    }
    if (PACK) {
        uint4 o;
        o.x = h2u(__floats2half2_rn(vv[0], vv[1]));
        o.y = h2u(__floats2half2_rn(vv[2], vv[3]));
        o.z = h2u(__floats2half2_rn(vv[4], vv[5]));
        o.w = h2u(__floats2half2_rn(vv[6], vv[7]));
        *(uint4*)&g_a2[(size_t)gw * 128 + lane * 4] = o;
    } else {
        float4* dst = (float4*)(out + (size_t)gw * HC + lane * 8);
        dst[0] = make_float4(vv[0], vv[1], vv[2], vv[3]);
        dst[1] = make_float4(vv[4], vv[5], vv[6], vv[7]);
    }
}

// ---------------- pooling + MLP head ----------------
__global__ void k_pool(const float* __restrict__ h3) {
    int g = blockIdx.x;
    int c = threadIdx.x;
    int s = g_goff[g], e = g_goff[g + 1];
    float sum = 0.f;
    for (int n = s; n < e; n++) sum += h3[(size_t)n * HC + c];
    float cntf = (float)(e - s);
    g_pooled[g * HC + c] = sum / fmaxf(cntf, 1.0f);
}

__global__ void k_mlp1(const float* __restrict__ Wm1, const float* __restrict__ bm1) {
    __shared__ float sp[HC];
    int g = blockIdx.x;
    int j = threadIdx.x;
    if (j < HC) sp[j] = g_pooled[g * HC + j];
    __syncthreads();
    float acc = __ldg(&bm1[j]);
    for (int k = 0; k < HC; k++) acc += sp[k] * __ldg(&Wm1[(size_t)k * NHID + j]);
    g_hid[g * NHID + j] = fmaxf(acc, 0.f);
}

__global__ void k_mlp2(const float* __restrict__ Wm2, const float* __restrict__ bm2,
                       float* __restrict__ out) {
    __shared__ float sp[NHID];
    int g = blockIdx.x;
    int j = threadIdx.x;
    for (int k = j; k < NHID; k += NOUT) sp[k] = g_hid[g * NHID + k];
    __syncthreads();
    float acc = __ldg(&bm2[j]);
    for (int k = 0; k < NHID; k++) acc += sp[k] * __ldg(&Wm2[(size_t)k * NOUT + j]);
    out[g * NOUT + j] = acc;
}

// ---------------- launch ----------------
extern "C" void kernel_launch(void* const* d_in, const int* in_sizes, int n_in,
                              void* d_out, int out_size) {
    const float* x     = (const float*)d_in[0];
    const void*  ei    = d_in[1];
    const void*  batch = d_in[2];
    const float* W1  = (const float*)d_in[3];
    const float* as1 = (const float*)d_in[4];
    const float* ad1 = (const float*)d_in[5];
    const float* b1  = (const float*)d_in[6];
    const float* W2  = (const float*)d_in[7];
    const float* as2 = (const float*)d_in[8];
    const float* ad2 = (const float*)d_in[9];
    const float* b2  = (const float*)d_in[10];
    const float* W3  = (const float*)d_in[11];
    const float* as3 = (const float*)d_in[12];
    const float* ad3 = (const float*)d_in[13];
    const float* b3  = (const float*)d_in[14];
    const float* Wm1 = (const float*)d_in[15];
    const float* bm1 = (const float*)d_in[16];
    const float* Wm2 = (const float*)d_in[17];
    const float* bm2 = (const float*)d_in[18];
    float* out = (float*)d_out;

    float* bufB;
    __half2* h16;
    unsigned* a2;
    uint2 *bf1, *bf2, *bf3;
    cudaGetSymbolAddress((void**)&bufB, g_bufB);
    cudaGetSymbolAddress((void**)&h16, g_h16);
    cudaGetSymbolAddress((void**)&a2, g_a2);
    cudaGetSymbolAddress((void**)&bf1, g_bf1);
    cudaGetSymbolAddress((void**)&bf2, g_bf2);
    cudaGetSymbolAddress((void**)&bf3, g_bf3);

    const int TPB = 256;
    int nb_node = (NN + TPB - 1) / TPB;          // 157
    int nb_edge = (EE + TPB - 1) / TPB;
    int nb_warp = (NN * 32 + TPB - 1) / TPB;
    int nb_prep = (NN * 128 + TPB - 1) / TPB;

    dim3 gemm_grid(NN / 64, 2);

    // launch index 3 (0-based) is what ncu captures -> keep gemm there
    k_prep<<<nb_prep, TPB>>>(x, W1, W2, W3, ei, batch);          // 0
    k_count<<<nb_edge, TPB>>>(ei);                               // 1
    k_scan1<<<nb_node, TPB>>>();                                 // 2
    k_gemm<<<gemm_grid, 128>>>(a2, bf1, as1, ad1, h16);          // 3  <- profiled
    k_scan2<<<1, 256>>>(nb_node);                                // 4
    k_scan3<<<nb_node, TPB>>>();                                 // 5
    k_fill<<<nb_edge, TPB>>>(ei);                                // 6
    k_gbounds<<<1, 128>>>(batch);                                // 7

    // Layer 1 (gemm + alpha already done)
    k_gather<true, true><<<nb_warp, TPB>>>(h16, b1, bufB);

    // Layer 2
    k_gemm<<<gemm_grid, 128>>>(a2, bf2, as2, ad2, h16);
    k_gather<true, true><<<nb_warp, TPB>>>(h16, b2, bufB);

    // Layer 3 (no relu, fp32 out for pooling)
    k_gemm<<<gemm_grid, 128>>>(a2, bf3, as3, ad3, h16);
    k_gather<false, false><<<nb_warp, TPB>>>(h16, b3, bufB);

    // Pool + MLP
    k_pool<<<GG, HC>>>(bufB);
    k_mlp1<<<GG, NHID>>>(Wm1, bm1);
    k_mlp2<<<GG, NOUT>>>(Wm2, bm2, out);
}

// round 11
// speedup vs baseline: 2.4613x; 1.0433x over previous
#include <cuda_runtime.h>
#include <cuda_fp16.h>
#include <math.h>
#include <stdint.h>

#define NN   40000
#define EE   640000
#define GG   64
#define HH   4
#define CC   64
#define HC   256
#define NHID 1024
#define NOUT 768
#define NEG_SLOPE 0.2f

// ---------------- static device scratch ----------------
__device__ __half2 g_h16[(size_t)NN * 128];      // gemm output h (fp16 pairs) for gather
__device__ float g_bufB[(size_t)NN * HC];        // layer-3 gather output (fp32)
__device__ unsigned g_a2[(size_t)NN * 128];      // gemm input: fp16 pair per k-pair
__device__ float g_as[NN * 4];
__device__ float g_ad[NN * 4];
__device__ int   g_cnt[NN];
__device__ int   g_cur[NN];
__device__ int   g_off[NN + 1];
__device__ int   g_csr[EE];
__device__ int   g_goff[GG + 1];
__device__ float g_pooled[GG * HC];
__device__ float g_hid[GG * NHID];
__device__ int   g_is64_e, g_is64_b;
__device__ int   g_bsum[160];
__device__ int   g_boff[160];
// B in mma-fragment order: idx = (ntg*16 + kc)*32 + lane, uint2 = {b0, b1} fp16x2
__device__ uint2 g_bf1[16384], g_bf2[16384], g_bf3[16384];

__device__ __forceinline__ float lrelu(float v) {
    return v > 0.f ? v : NEG_SLOPE * v;
}

__device__ __forceinline__ int idx_at(const void* p, long long i, int is64) {
    if (is64) return (int)((const long long*)p)[i];
    return ((const int*)p)[i];
}

__device__ __forceinline__ unsigned h2u(__half2 h) { return *(unsigned*)&h; }

// ---------------- prep: detect dtypes + zero counters + weight fragments + split x ----------------
__global__ void k_prep(const float* __restrict__ x,
                       const float* __restrict__ W1, const float* __restrict__ W2,
                       const float* __restrict__ W3,
                       const void* ei, const void* batch) {
    int i = blockIdx.x * blockDim.x + threadIdx.x;

    if (blockIdx.x == 0 && threadIdx.x < 32) {
        int lane = threadIdx.x;
        const int* e32 = (const int*)ei;
        int nz = 0;
        for (int j = lane; j < 64; j += 32) nz |= (e32[2 * j + 1] != 0);
        nz = __any_sync(0xffffffffu, nz);
        if (lane == 0) g_is64_e = !nz;
        const int* b32 = (const int*)batch;
        int nzb = (b32[NN - 1 - 2 * lane] != 0);
        nzb = __any_sync(0xffffffffu, nzb);
        if (lane == 0) g_is64_b = !nzb;
    }

    if (i < NN) { g_cnt[i] = 0; g_cur[i] = 0; }

    if (i < 16384) {
        int ntg = i >> 9;
        int kc  = (i >> 5) & 15;
        int lane = i & 31;
        int lm = lane >> 2, lk = lane & 3;
        int n = ntg * 8 + lm;
        int k0 = kc * 16 + 2 * lk;
        uint2 f;
        f.x = h2u(__floats2half2_rn(W1[(size_t)k0 * 256 + n], W1[(size_t)(k0 + 1) * 256 + n]));
        f.y = h2u(__floats2half2_rn(W1[(size_t)(k0 + 8) * 256 + n], W1[(size_t)(k0 + 9) * 256 + n]));
        g_bf1[i] = f;
        f.x = h2u(__floats2half2_rn(W2[(size_t)k0 * 256 + n], W2[(size_t)(k0 + 1) * 256 + n]));
        f.y = h2u(__floats2half2_rn(W2[(size_t)(k0 + 8) * 256 + n], W2[(size_t)(k0 + 9) * 256 + n]));
        g_bf2[i] = f;
        f.x = h2u(__floats2half2_rn(W3[(size_t)k0 * 256 + n], W3[(size_t)(k0 + 1) * 256 + n]));
        f.y = h2u(__floats2half2_rn(W3[(size_t)(k0 + 8) * 256 + n], W3[(size_t)(k0 + 9) * 256 + n]));
        g_bf3[i] = f;
    }

    if (i < NN * 128) {
        float2 v = ((const float2*)x)[i];
        g_a2[i] = h2u(__floats2half2_rn(v.x, v.y));
    }
}

// ---------------- CSR ----------------
__global__ void k_count(const void* __restrict__ ei) {
    int e = blockIdx.x * blockDim.x + threadIdx.x;
    if (e < EE) atomicAdd(&g_cnt[idx_at(ei, (long long)EE + e, g_is64_e)], 1);
}

__global__ void k_gbounds(const void* __restrict__ batch) {
    int g = threadIdx.x;
    if (g > GG) return;
    int is64 = g_is64_b;
    int lo = 0, hi = NN;
    while (lo < hi) {
        int mid = (lo + hi) >> 1;
        if (idx_at(batch, mid, is64) < g) lo = mid + 1; else hi = mid;
    }
    g_goff[g] = lo;
}

__global__ void k_scan1() {
    __shared__ int sd[256];
    int b = blockIdx.x, t = threadIdx.x;
    int i = b * 256 + t;
    int v = (i < NN) ? g_cnt[i] : 0;
    sd[t] = v;
    __syncthreads();
#pragma unroll
    for (int o = 1; o < 256; o <<= 1) {
        int y = (t >= o) ? sd[t - o] : 0;
        __syncthreads();
        sd[t] += y;
        __syncthreads();
    }
    if (i < NN) g_off[i] = sd[t] - v;
    if (t == 255) g_bsum[b] = sd[255];
}

__global__ void k_scan2(int nb) {
    __shared__ int sd[256];
    int t = threadIdx.x;
    int v = (t < nb) ? g_bsum[t] : 0;
    sd[t] = v;
    __syncthreads();
#pragma unroll
    for (int o = 1; o < 256; o <<= 1) {
        int y = (t >= o) ? sd[t - o] : 0;
        __syncthreads();
        sd[t] += y;
        __syncthreads();
    }
    if (t < nb) g_boff[t] = sd[t] - v;
    if (t == 0) g_off[NN] = EE;
}

__global__ void k_scan3() {
    int i = blockIdx.x * blockDim.x + threadIdx.x;
    if (i < NN) g_off[i] += g_boff[blockIdx.x];
}

__global__ void k_fill(const void* __restrict__ ei) {
    int e = blockIdx.x * blockDim.x + threadIdx.x;
    if (e >= EE) return;
    int is64 = g_is64_e;
    int s = idx_at(ei, e, is64);
    int d = idx_at(ei, (long long)EE + e, is64);
    int pos = atomicAdd(&g_cur[d], 1);
    g_csr[g_off[d] + pos] = s;
}

// ---------------- fp16 tensor-core GEMM: smem-staged A + ldmatrix, fragment-ordered B in L1 ----------------
// h[M,256] = A[M,256] @ B[256,256]; fp16 inputs, fp32 accumulate.
// Block: 64x128 tile, 128 threads (4 warps, 2m x 2n), warp tile 32x64 = one full head.
// A staged to smem (row stride 528B -> conflict-free ldmatrix), fragments via ldmatrix.x4.

__device__ __forceinline__ void mma_f16(float* d, unsigned a0, unsigned a1, unsigned a2,
                                        unsigned a3, unsigned b0, unsigned b1) {
    asm volatile(
        "mma.sync.aligned.m16n8k16.row.col.f32.f16.f16.f32 "
        "{%0,%1,%2,%3}, {%4,%5,%6,%7}, {%8,%9}, {%0,%1,%2,%3};\n"
        : "+f"(d[0]), "+f"(d[1]), "+f"(d[2]), "+f"(d[3])
        : "r"(a0), "r"(a1), "r"(a2), "r"(a3), "r"(b0), "r"(b1));
}

#define SA_STR 132   // uints per A smem row (128 + 4 pad -> 528B, banks 4r mod 32)

__global__ void __launch_bounds__(128, 4) k_gemm(const unsigned* __restrict__ A2,
                                                 const uint2* __restrict__ Bf,
                                                 const float* __restrict__ a_s,
                                                 const float* __restrict__ a_d,
                                                 __half2* __restrict__ Hout) {
    __shared__ __align__(16) unsigned sA[64 * SA_STR];

    int tid = threadIdx.x;
    int warp = tid >> 5, lane = tid & 31;
    int lm = lane >> 2, lk = lane & 3;
    int wm = warp & 1, wc = warp >> 1;
    int rowblk = blockIdx.x * 64;
    int row0 = rowblk + wm * 32;
    int ntg0 = blockIdx.y * 16 + wc * 8;

    // ---- stage A tile (64 rows x 512B) coalesced ----
    {
        int r = tid & 63, hf = tid >> 6;
        const uint4* src = (const uint4*)(A2 + (size_t)(rowblk + r) * 128 + hf * 64);
        uint4* dst = (uint4*)(sA + r * SA_STR + hf * 64);
#pragma unroll
        for (int i = 0; i < 16; i++) dst[i] = __ldg(src + i);
    }
    __syncthreads();

    float acc[2][8][4];
#pragma unroll
    for (int mt = 0; mt < 2; mt++)
#pragma unroll
        for (int nt = 0; nt < 8; nt++)
#pragma unroll
            for (int r = 0; r < 4; r++) acc[mt][nt][r] = 0.f;

    const uint2* bp = Bf + ntg0 * 512 + lane;

    // ldmatrix lane address: tile = lane>>3 -> (m8 offset = tile&1, k8 offset = tile>>1)
    int tile = lane >> 3, tr = lane & 7;
    unsigned sbase = (unsigned)__cvta_generic_to_shared(sA);
    unsigned aaddr = sbase + (((wm * 32 + (tile & 1) * 8 + tr) * SA_STR) + (tile >> 1) * 4) * 4;

#pragma unroll
    for (int kc = 0; kc < 16; kc++) {
        unsigned af[2][4];
#pragma unroll
        for (int mt = 0; mt < 2; mt++) {
            unsigned a = aaddr + mt * (16 * SA_STR * 4) + kc * 32;
            asm volatile(
                "ldmatrix.sync.aligned.m8n8.x4.shared.b16 {%0,%1,%2,%3}, [%4];"
                : "=r"(af[mt][0]), "=r"(af[mt][1]), "=r"(af[mt][2]), "=r"(af[mt][3])
                : "r"(a));
        }
        uint2 bb[8];
#pragma unroll
        for (int nt = 0; nt < 8; nt++)
            bb[nt] = __ldg(bp + nt * 512 + kc * 32);
#pragma unroll
        for (int mt = 0; mt < 2; mt++)
#pragma unroll
            for (int nt = 0; nt < 8; nt++)
                mma_f16(acc[mt][nt], af[mt][0], af[mt][1], af[mt][2], af[mt][3],
                        bb[nt].x, bb[nt].y);
    }

    // ---- epilogue 1: store h as half2 ----
#pragma unroll
    for (int mt = 0; mt < 2; mt++) {
        int r = row0 + mt * 16 + lm;
#pragma unroll
        for (int nt = 0; nt < 8; nt++) {
            int kp = ((ntg0 + nt) * 8 + lk * 2) >> 1;
            Hout[(size_t)r * 128 + kp]       = __floats2half2_rn(acc[mt][nt][0], acc[mt][nt][1]);
            Hout[(size_t)(r + 8) * 128 + kp] = __floats2half2_rn(acc[mt][nt][2], acc[mt][nt][3]);
        }
    }

    // ---- epilogue 2: fused alpha (warp's 64 cols = one full head) ----
    int hh = blockIdx.y * 2 + wc;
#pragma unroll
    for (int mt = 0; mt < 2; mt++) {
#pragma unroll
        for (int b = 0; b < 2; b++) {
            float s = 0.f, d = 0.f;
#pragma unroll
            for (int nt = 0; nt < 8; nt++) {
                int c = (ntg0 + nt) * 8 + lk * 2;
                float v0 = acc[mt][nt][2 * b], v1 = acc[mt][nt][2 * b + 1];
                s += v0 * __ldg(&a_s[c]) + v1 * __ldg(&a_s[c + 1]);
                d += v0 * __ldg(&a_d[c]) + v1 * __ldg(&a_d[c + 1]);
            }
            s += __shfl_xor_sync(0xffffffffu, s, 1);
            s += __shfl_xor_sync(0xffffffffu, s, 2);
            d += __shfl_xor_sync(0xffffffffu, d, 1);
            d += __shfl_xor_sync(0xffffffffu, d, 2);
            if (lk == 0) {
                int row = row0 + mt * 16 + lm + 8 * b;
                g_as[row * 4 + hh] = s;
                g_ad[row * 4 + hh] = d;
            }
        }
    }
}

// ---------------- warp-per-node gather: lane owns cols [8l, 8l+8), head q = l>>3 ----------------
template <bool RELU, bool PACK>
__global__ void k_gather(const __half2* __restrict__ h, const float* __restrict__ bias,
                         float* __restrict__ out) {
    int gw = (blockIdx.x * blockDim.x + threadIdx.x) >> 5;
    int lane = threadIdx.x & 31;
    if (gw >= NN) return;
    int q = lane >> 3;
    int s0 = g_off[gw], s1 = g_off[gw + 1];
    float dvq = __ldg(&g_ad[gw * 4 + q]);

    float acc[8];
#pragma unroll
    for (int j = 0; j < 8; j++) acc[j] = 0.f;
    float den = 0.f;

    const uint4* hb = (const uint4*)h;
    int snext = (s0 < s1) ? __ldg(&g_csr[s0]) : 0;
    for (int i = s0; i < s1; i++) {
        int s = snext;
        if (i + 1 < s1) snext = __ldg(&g_csr[i + 1]);
        float aq = __ldg(&g_as[s * 4 + q]);
        float w = __expf(lrelu(aq + dvq));
        den += w;
        uint4 v = __ldg(hb + (size_t)s * 32 + lane);
        float2 f0 = __half22float2(*(__half2*)&v.x);
        float2 f1 = __half22float2(*(__half2*)&v.y);
        float2 f2 = __half22float2(*(__half2*)&v.z);
        float2 f3 = __half22float2(*(__half2*)&v.w);
        acc[0] += w * f0.x; acc[1] += w * f0.y;
        acc[2] += w * f1.x; acc[3] += w * f1.y;
        acc[4] += w * f2.x; acc[5] += w * f2.y;
        acc[6] += w * f3.x; acc[7] += w * f3.y;
    }
    // self loop
    float asq = __ldg(&g_as[gw * 4 + q]);
    float wsl = __expf(lrelu(asq + dvq));
    den += wsl;
    uint4 hv = __ldg(hb + (size_t)gw * 32 + lane);
    float2 h0 = __half22float2(*(__half2*)&hv.x);
    float2 h1 = __half22float2(*(__half2*)&hv.y);
    float2 h2 = __half22float2(*(__half2*)&hv.z);
    float2 h3 = __half22float2(*(__half2*)&hv.w);
    float hf[8] = {h0.x, h0.y, h1.x, h1.y, h2.x, h2.y, h3.x, h3.y};

    float4 b0 = __ldg((const float4*)bias + lane * 2);
    float4 b1 = __ldg((const float4*)bias + lane * 2 + 1);
    float bf[8] = {b0.x, b0.y, b0.z, b0.w, b1.x, b1.y, b1.z, b1.w};

    float inv = 1.f / den;
    float vv[8];
#pragma unroll
    for (int j = 0; j < 8; j++) {
        float v = (acc[j] + wsl * hf[j]) * inv + bf[j];
        if (RELU) v = fmaxf(v, 0.f);
        vv[j] = v;
    }
    if (PACK) {
        uint4 o;
        o.x = h2u(__floats2half2_rn(vv[0], vv[1]));
        o.y = h2u(__floats2half2_rn(vv[2], vv[3]));
        o.z = h2u(__floats2half2_rn(vv[4], vv[5]));
        o.w = h2u(__floats2half2_rn(vv[6], vv[7]));
        *(uint4*)&g_a2[(size_t)gw * 128 + lane * 4] = o;
    } else {
        float4* dst = (float4*)(out + (size_t)gw * HC + lane * 8);
        dst[0] = make_float4(vv[0], vv[1], vv[2], vv[3]);
        dst[1] = make_float4(vv[4], vv[5], vv[6], vv[7]);
    }
}

// ---------------- pooling + MLP head ----------------
__global__ void k_pool(const float* __restrict__ h3) {
    int g = blockIdx.x;
    int c = blockIdx.y * 128 + threadIdx.x;
    int s = g_goff[g], e = g_goff[g + 1];
    float sum = 0.f;
    for (int n = s; n < e; n++) sum += h3[(size_t)n * HC + c];
    float cntf = (float)(e - s);
    g_pooled[g * HC + c] = sum / fmaxf(cntf, 1.0f);
}

__global__ void k_mlp1(const float* __restrict__ Wm1, const float* __restrict__ bm1) {
    __shared__ float sp[HC];
    int g = blockIdx.x;
    int j = threadIdx.x;
    if (j < HC) sp[j] = g_pooled[g * HC + j];
    __syncthreads();
    float acc = __ldg(&bm1[j]);
    for (int k = 0; k < HC; k++) acc += sp[k] * __ldg(&Wm1[(size_t)k * NHID + j]);
    g_hid[g * NHID + j] = fmaxf(acc, 0.f);
}

__global__ void k_mlp2(const float* __restrict__ Wm2, const float* __restrict__ bm2,
                       float* __restrict__ out) {
    __shared__ float sp[NHID];
    int g = blockIdx.x;
    int j = threadIdx.x;
    for (int k = j; k < NHID; k += NOUT) sp[k] = g_hid[g * NHID + k];
    __syncthreads();
    float acc = __ldg(&bm2[j]);
    for (int k = 0; k < NHID; k++) acc += sp[k] * __ldg(&Wm2[(size_t)k * NOUT + j]);
    out[g * NOUT + j] = acc;
}

// ---------------- launch ----------------
extern "C" void kernel_launch(void* const* d_in, const int* in_sizes, int n_in,
                              void* d_out, int out_size) {
    const float* x     = (const float*)d_in[0];
    const void*  ei    = d_in[1];
    const void*  batch = d_in[2];
    const float* W1  = (const float*)d_in[3];
    const float* as1 = (const float*)d_in[4];
    const float* ad1 = (const float*)d_in[5];
    const float* b1  = (const float*)d_in[6];
    const float* W2  = (const float*)d_in[7];
    const float* as2 = (const float*)d_in[8];
    const float* ad2 = (const float*)d_in[9];
    const float* b2  = (const float*)d_in[10];
    const float* W3  = (const float*)d_in[11];
    const float* as3 = (const float*)d_in[12];
    const float* ad3 = (const float*)d_in[13];
    const float* b3  = (const float*)d_in[14];
    const float* Wm1 = (const float*)d_in[15];
    const float* bm1 = (const float*)d_in[16];
    const float* Wm2 = (const float*)d_in[17];
    const float* bm2 = (const float*)d_in[18];
    float* out = (float*)d_out;

    float* bufB;
    __half2* h16;
    unsigned* a2;
    uint2 *bf1, *bf2, *bf3;
    cudaGetSymbolAddress((void**)&bufB, g_bufB);
    cudaGetSymbolAddress((void**)&h16, g_h16);
    cudaGetSymbolAddress((void**)&a2, g_a2);
    cudaGetSymbolAddress((void**)&bf1, g_bf1);
    cudaGetSymbolAddress((void**)&bf2, g_bf2);
    cudaGetSymbolAddress((void**)&bf3, g_bf3);

    const int TPB = 256;
    int nb_node = (NN + TPB - 1) / TPB;          // 157
    int nb_edge = (EE + TPB - 1) / TPB;
    int nb_warp = (NN * 32 + TPB - 1) / TPB;
    int nb_prep = (NN * 128 + TPB - 1) / TPB;

    dim3 gemm_grid(NN / 64, 2);

    // launch index 3 (0-based) is what ncu captures -> keep gemm there
    k_prep<<<nb_prep, TPB>>>(x, W1, W2, W3, ei, batch);          // 0
    k_count<<<nb_edge, TPB>>>(ei);                               // 1
    k_scan1<<<nb_node, TPB>>>();                                 // 2
    k_gemm<<<gemm_grid, 128>>>(a2, bf1, as1, ad1, h16);          // 3  <- profiled
    k_scan2<<<1, 256>>>(nb_node);                                // 4
    k_scan3<<<nb_node, TPB>>>();                                 // 5
    k_fill<<<nb_edge, TPB>>>(ei);                                // 6
    k_gbounds<<<1, 128>>>(batch);                                // 7

    // Layer 1 (gemm + alpha already done)
    k_gather<true, true><<<nb_warp, TPB>>>(h16, b1, bufB);

    // Layer 2
    k_gemm<<<gemm_grid, 128>>>(a2, bf2, as2, ad2, h16);
    k_gather<true, true><<<nb_warp, TPB>>>(h16, b2, bufB);

    // Layer 3 (no relu, fp32 out for pooling)
    k_gemm<<<gemm_grid, 128>>>(a2, bf3, as3, ad3, h16);
    k_gather<false, false><<<nb_warp, TPB>>>(h16, b3, bufB);

    // Pool + MLP
    k_pool<<<dim3(GG, 2), 128>>>(bufB);
    k_mlp1<<<GG, NHID>>>(Wm1, bm1);
    k_mlp2<<<GG, NOUT>>>(Wm2, bm2, out);
}